// round 15
// baseline (speedup 1.0000x reference)
#include <cuda_runtime.h>
#include <cuda_fp16.h>
#include <math.h>
#include <stdint.h>

// ---------------- problem constants ----------------
#define SEQ 2048
#define HID 2560
#define NH 40
#define DQK 96
#define DV 64
#define RD 32
#define QA_DIM 768
#define KVA_DIM 288
#define CKV_DIM 256
#define QB_DIM (NH*DQK)         // 3840
#define KVB_DIM (NH*(64+DV))    // 5120
#define OUT_DIM 2560
#define EPSV 1e-6f
#define QSCALE_L2E 0.14724602233502312f   // 96^-0.5 * log2(e)

// ---------------- scratch ----------------
__device__ __half g_qa0 [SEQ*QA_DIM];
__device__ __half g_qa1 [SEQ*QA_DIM];
__device__ __half g_ckv0[SEQ*KVA_DIM];
__device__ __half g_ckv1[SEQ*KVA_DIM];
__device__ float  g_o1  [SEQ*OUT_DIM];
__device__ __half g_hidh[SEQ*HID];
__device__ __half g_wqaT[QA_DIM*HID];
__device__ __half g_wkvaT[KVA_DIM*HID];
__device__ __half g_wqbT[QB_DIM*QA_DIM];
__device__ __half g_wkvbT[KVB_DIM*CKV_DIM];
__device__ __half g_woT [OUT_DIM*(NH*DV)];
__device__ __half g_qan [SEQ*QA_DIM];
__device__ __half g_ckvn[SEQ*CKV_DIM];
__device__ __half g_Q   [NH*SEQ*DQK];
__device__ __half g_K   [NH*SEQ*DQK];
__device__ __half g_Vt  [NH*DV*SEQ];
__device__ __half g_attn[SEQ*NH*DV];

// ---------------- helpers ----------------
__device__ __forceinline__ float ex2f(float x) {
    float r;
    asm("ex2.approx.ftz.f32 %0, %1;" : "=f"(r) : "f"(x));
    return r;
}
__device__ __forceinline__ void cp16(uint32_t dst, const void* src, bool pred) {
    int sz = pred ? 16 : 0;
    asm volatile("cp.async.cg.shared.global [%0], [%1], 16, %2;\n"
                 :: "r"(dst), "l"(src), "r"(sz));
}
__device__ __forceinline__ void cp_commit() {
    asm volatile("cp.async.commit_group;\n");
}
template <int N>
__device__ __forceinline__ void cp_wait() {
    asm volatile("cp.async.wait_group %0;\n" :: "n"(N));
}

#define MMA_F16(c, a, b) \
    asm volatile("mma.sync.aligned.m16n8k16.row.col.f32.f16.f16.f32 " \
                 "{%0,%1,%2,%3},{%4,%5,%6,%7},{%8,%9},{%0,%1,%2,%3};" \
                 : "+f"(c[0]), "+f"(c[1]), "+f"(c[2]), "+f"(c[3]) \
                 : "r"(a[0]), "r"(a[1]), "r"(a[2]), "r"(a[3]), \
                   "r"(b[0]), "r"(b[1]))

#define LDSM4(r, addr) \
    asm volatile("ldmatrix.sync.aligned.m8n8.x4.shared.b16 {%0,%1,%2,%3}, [%4];" \
                 : "=r"((r)[0]), "=r"((r)[1]), "=r"((r)[2]), "=r"((r)[3]) \
                 : "r"(addr))

__device__ __forceinline__ uint32_t packh2(float a, float b) {
    __half2 h = __floats2half2_rn(a, b);
    return *reinterpret_cast<uint32_t*>(&h);
}

// ================= convert / transpose pass =================
struct CV6 {
    const float* src[6];
    __half* dst[6];
    int K[6], N[6];
    int nbx[6];
    int bstart[7];
    int trans[6];
};
__global__ __launch_bounds__(256) void convtrans(CV6 p) {
    __shared__ __half sm[64 * 72];
    int bid = blockIdx.x;
    int pi = 0;
#pragma unroll
    for (int i = 1; i < 6; i++) if (bid >= p.bstart[i]) pi = i;
    int l = bid - p.bstart[pi];
    int tid = threadIdx.x;
    if (p.trans[pi]) {
        int K = p.K[pi], N = p.N[pi];
        int k0 = (l / p.nbx[pi]) * 64;
        int n0 = (l % p.nbx[pi]) * 64;
        const float* src = p.src[pi];
#pragma unroll
        for (int i = 0; i < 4; i++) {
            int idx = tid + i * 256;
            int r = idx >> 4, c4 = idx & 15;
            int n = n0 + c4 * 4;
            if (n < N) {
                float4 v = *reinterpret_cast<const float4*>(
                    &src[(size_t)(k0 + r) * N + n]);
                sm[(c4 * 4 + 0) * 72 + r] = __float2half_rn(v.x);
                sm[(c4 * 4 + 1) * 72 + r] = __float2half_rn(v.y);
                sm[(c4 * 4 + 2) * 72 + r] = __float2half_rn(v.z);
                sm[(c4 * 4 + 3) * 72 + r] = __float2half_rn(v.w);
            }
        }
        __syncthreads();
        __half* dst = p.dst[pi];
#pragma unroll
        for (int i = 0; i < 2; i++) {
            int idx = tid + i * 256;
            int rr = idx >> 3, cc = idx & 7;
            if (n0 + rr < N) {
                uint4 v = *reinterpret_cast<const uint4*>(&sm[rr * 72 + cc * 8]);
                *reinterpret_cast<uint4*>(
                    &dst[(size_t)(n0 + rr) * K + k0 + cc * 8]) = v;
            }
        }
    } else {
        const float* src = p.src[pi];
        __half* dst = p.dst[pi];
        int base = l * 4096;
#pragma unroll
        for (int i = 0; i < 4; i++) {
            int e = base + (tid + i * 256) * 4;
            float4 v = *reinterpret_cast<const float4*>(&src[e]);
            __half2 h0 = __floats2half2_rn(v.x, v.y);
            __half2 h1 = __floats2half2_rn(v.z, v.w);
            *reinterpret_cast<__half2*>(&dst[e]) = h0;
            *reinterpret_cast<__half2*>(&dst[e + 2]) = h1;
        }
    }
}

// ======= shared GEMM config (128x128x64, 3-stage, ldmatrix) ===========
#define HSTR 72
#define HBUF (128*HSTR)
#define HG_SMEM_BYTES (3*2*HBUF*2)      // 110592

struct GP4 {
    const __half* A[4];
    const __half* B[4];   // BT [N][K]
    float*        C[4];
    int N[4], K[4], lda[4], ldb[4], nbx[4], bstart[4];
    int mode[4];          // 0=fp32 out, 1=half out; fused: 2=Q, 3=KV
    int nprob;
    const float* cosp;
    const float* sinp;
    __half* Qp;
    __half* Kp;
    __half* Vtp;
};

// ===== hgemm4: 128x128x64, 4 warps (64x64 warp tile), 128 thr, 2 CTA/SM ====
__global__ __launch_bounds__(128, 2) void hgemm4(GP4 p) {
    extern __shared__ __half hsm[];
    uint32_t sm_u = (uint32_t)__cvta_generic_to_shared(hsm);

    int bid = blockIdx.x;
    int pi = 0;
#pragma unroll
    for (int i = 1; i < 4; i++)
        if (i < p.nprob && bid >= p.bstart[i]) pi = i;
    const __half* A = p.A[pi];
    const __half* B = p.B[pi];
    int N = p.N[pi], K = p.K[pi], lda = p.lda[pi], ldb = p.ldb[pi];
    int mode = p.mode[pi];
    int l = bid - p.bstart[pi];
    int row0 = (l / p.nbx[pi]) * 128;
    int col0 = (l % p.nbx[pi]) * 128;

    int tid = threadIdx.x;
    int warp = tid >> 5, lane = tid & 31;
    int g = lane >> 2, t = lane & 3;
    int wrow = (warp >> 1) * 64;
    int wcol = (warp & 1) * 64;
    int arow = lane & 15;
    int acol = (lane >> 4) * 8;
    int brow = ((lane >> 4) & 1) * 8 + (lane & 7);
    int bcol = ((lane >> 3) & 1) * 8;

    float c[4][8][4];
#pragma unroll
    for (int mi = 0; mi < 4; mi++)
#pragma unroll
        for (int ni = 0; ni < 8; ni++)
#pragma unroll
            for (int r = 0; r < 4; r++) c[mi][ni][r] = 0.f;

    int kt_total = K / 64;

    auto load_tile = [&](int kt, int stg) {
        int k0 = kt * 64;
        uint32_t aD = sm_u + (uint32_t)(stg * 2 * HBUF * 2);
        uint32_t bD = aD + (uint32_t)(HBUF * 2);
#pragma unroll
        for (int i = 0; i < 8; i++) {
            int idx = tid + i * 128;
            int r = idx >> 3, cc = (idx & 7) * 8;
            cp16(aD + (uint32_t)((r * HSTR + cc) * 2),
                 A + (size_t)(row0 + r) * lda + k0 + cc, true);
        }
#pragma unroll
        for (int i = 0; i < 8; i++) {
            int idx = tid + i * 128;
            int r = idx >> 3, cc = (idx & 7) * 8;
            bool pr = (col0 + r) < N;
            const __half* src = pr ? (B + (size_t)(col0 + r) * ldb + k0 + cc) : B;
            cp16(bD + (uint32_t)((r * HSTR + cc) * 2), src, pr);
        }
    };

    load_tile(0, 0); cp_commit();
    load_tile(1, 1); cp_commit();

    int s_cur = 0, s_next = 2;
    for (int kt = 0; kt < kt_total; kt++) {
        cp_wait<1>();
        __syncthreads();
        if (kt + 2 < kt_total) load_tile(kt + 2, s_next);
        cp_commit();

        uint32_t aBase = sm_u + (uint32_t)(s_cur * 2 * HBUF * 2);
        uint32_t bBase = aBase + (uint32_t)(HBUF * 2);
#pragma unroll
        for (int k0 = 0; k0 < 64; k0 += 16) {
            uint32_t a[4][4], bb[4][4];
#pragma unroll
            for (int mi = 0; mi < 4; mi++)
                LDSM4(a[mi], aBase + (uint32_t)(((wrow + mi * 16 + arow) * HSTR
                                                 + k0 + acol) * 2));
#pragma unroll
            for (int nip = 0; nip < 4; nip++)
                LDSM4(bb[nip], bBase + (uint32_t)(((wcol + nip * 16 + brow) * HSTR
                                                   + k0 + bcol) * 2));
#pragma unroll
            for (int mi = 0; mi < 4; mi++)
#pragma unroll
                for (int ni = 0; ni < 8; ni++)
                    MMA_F16(c[mi][ni], a[mi], (&bb[ni >> 1][2 * (ni & 1)]));
        }
        s_cur = (s_cur == 2) ? 0 : s_cur + 1;
        s_next = (s_next == 2) ? 0 : s_next + 1;
    }

    if (mode == 1) {
        __half* Ch = reinterpret_cast<__half*>(p.C[pi]);
#pragma unroll
        for (int mi = 0; mi < 4; mi++) {
#pragma unroll
            for (int ni = 0; ni < 8; ni++) {
                int row = row0 + wrow + mi * 16 + g;
                int col = col0 + wcol + ni * 8 + 2 * t;
                if (col < N) {
                    *reinterpret_cast<__half2*>(&Ch[(size_t)row * N + col]) =
                        __floats2half2_rn(c[mi][ni][0], c[mi][ni][1]);
                    *reinterpret_cast<__half2*>(&Ch[(size_t)(row + 8) * N + col]) =
                        __floats2half2_rn(c[mi][ni][2], c[mi][ni][3]);
                }
            }
        }
    } else {
        float* C = p.C[pi];
#pragma unroll
        for (int mi = 0; mi < 4; mi++) {
#pragma unroll
            for (int ni = 0; ni < 8; ni++) {
                int row = row0 + wrow + mi * 16 + g;
                int col = col0 + wcol + ni * 8 + 2 * t;
                if (col < N) {
                    float2 v0 = make_float2(c[mi][ni][0], c[mi][ni][1]);
                    float2 v1 = make_float2(c[mi][ni][2], c[mi][ni][3]);
                    *reinterpret_cast<float2*>(&C[(size_t)row * N + col]) = v0;
                    *reinterpret_cast<float2*>(&C[(size_t)(row + 8) * N + col]) = v1;
                }
            }
        }
    }
}

// ======= 8-warp GEMM body (kept for the fused epilogues) =======
template <typename EPI>
__device__ __forceinline__ void hgemm_body(const GP4& p, EPI epi) {
    extern __shared__ __half hsm[];
    uint32_t sm_u = (uint32_t)__cvta_generic_to_shared(hsm);

    int bid = blockIdx.x;
    int pi = 0;
#pragma unroll
    for (int i = 1; i < 4; i++)
        if (i < p.nprob && bid >= p.bstart[i]) pi = i;
    const __half* A = p.A[pi];
    const __half* B = p.B[pi];
    int N = p.N[pi], K = p.K[pi], lda = p.lda[pi], ldb = p.ldb[pi];
    int l = bid - p.bstart[pi];
    int row0 = (l / p.nbx[pi]) * 128;
    int col0 = (l % p.nbx[pi]) * 128;

    int tid = threadIdx.x;
    int warp = tid >> 5, lane = tid & 31;
    int wrow = (warp >> 2) * 64;
    int wcol = (warp & 3) * 32;
    int arow = lane & 15;
    int acol = (lane >> 4) * 8;
    int brow = ((lane >> 4) & 1) * 8 + (lane & 7);
    int bcol = ((lane >> 3) & 1) * 8;

    float c[4][4][4];
#pragma unroll
    for (int mi = 0; mi < 4; mi++)
#pragma unroll
        for (int ni = 0; ni < 4; ni++)
#pragma unroll
            for (int r = 0; r < 4; r++) c[mi][ni][r] = 0.f;

    int kt_total = K / 64;

    auto load_tile = [&](int kt, int stg) {
        int k0 = kt * 64;
        uint32_t aD = sm_u + (uint32_t)(stg * 2 * HBUF * 2);
        uint32_t bD = aD + (uint32_t)(HBUF * 2);
#pragma unroll
        for (int i = 0; i < 4; i++) {
            int idx = tid + i * 256;
            int r = idx >> 3, cc = (idx & 7) * 8;
            cp16(aD + (uint32_t)((r * HSTR + cc) * 2),
                 A + (size_t)(row0 + r) * lda + k0 + cc, true);
        }
#pragma unroll
        for (int i = 0; i < 4; i++) {
            int idx = tid + i * 256;
            int r = idx >> 3, cc = (idx & 7) * 8;
            bool pr = (col0 + r) < N;
            const __half* src = pr ? (B + (size_t)(col0 + r) * ldb + k0 + cc) : B;
            cp16(bD + (uint32_t)((r * HSTR + cc) * 2), src, pr);
        }
    };

    load_tile(0, 0); cp_commit();
    load_tile(1, 1); cp_commit();

    int s_cur = 0, s_next = 2;
    for (int kt = 0; kt < kt_total; kt++) {
        cp_wait<1>();
        __syncthreads();
        if (kt + 2 < kt_total) load_tile(kt + 2, s_next);
        cp_commit();

        uint32_t aBase = sm_u + (uint32_t)(s_cur * 2 * HBUF * 2);
        uint32_t bBase = aBase + (uint32_t)(HBUF * 2);
#pragma unroll
        for (int k0 = 0; k0 < 64; k0 += 16) {
            uint32_t a[4][4], bb[2][4];
#pragma unroll
            for (int mi = 0; mi < 4; mi++)
                LDSM4(a[mi], aBase + (uint32_t)(((wrow + mi * 16 + arow) * HSTR
                                                 + k0 + acol) * 2));
#pragma unroll
            for (int nip = 0; nip < 2; nip++)
                LDSM4(bb[nip], bBase + (uint32_t)(((wcol + nip * 16 + brow) * HSTR
                                                   + k0 + bcol) * 2));
#pragma unroll
            for (int mi = 0; mi < 4; mi++)
#pragma unroll
                for (int ni = 0; ni < 4; ni++)
                    MMA_F16(c[mi][ni], a[mi], (&bb[ni >> 1][2 * (ni & 1)]));
        }
        s_cur = (s_cur == 2) ? 0 : s_cur + 1;
        s_next = (s_next == 2) ? 0 : s_next + 1;
    }
    epi(pi, row0, col0, N, c);
}

// ---- fused GEMM (Q-rope / K+Vt epilogues) ----
__global__ __launch_bounds__(256, 2) void hgemm_fused(GP4 p) {
    extern __shared__ __half hsm[];
    int tid = threadIdx.x;
    int warp = tid >> 5, lane = tid & 31;
    int g = lane >> 2, t = lane & 3;
    int wrow = (warp >> 2) * 64;
    int wcol = (warp & 3) * 32;
    hgemm_body(p, [&](int pi, int row0, int col0, int N, float c[4][4][4]) {
        int mode = p.mode[pi];
        if (mode == 2) {
            int cb = col0 + wcol;
            int h = cb / 96;
            int rem = cb % 96;
            bool ropeBlk = (rem == 64);
            __half* Qg = p.Qp;
#pragma unroll
            for (int mi = 0; mi < 4; mi++) {
#pragma unroll
                for (int rr = 0; rr < 2; rr++) {
                    int srow = row0 + wrow + mi * 16 + g + 8 * rr;
                    const float* cosr = p.cosp + (size_t)srow * RD;
                    const float* sinr = p.sinp + (size_t)srow * RD;
#pragma unroll
                    for (int ni = 0; ni < 4; ni++) {
                        int dd = ni * 8 + 2 * t;
                        float v0 = c[mi][ni][2 * rr];
                        float v1 = c[mi][ni][2 * rr + 1];
                        if (ropeBlk) {
                            float cs0 = cosr[dd], sn0 = sinr[dd];
                            float cs1 = cosr[dd + 1], sn1 = sinr[dd + 1];
                            float r0, r1;
                            if (ni < 2) {
                                r0 = -c[mi][ni + 2][2 * rr];
                                r1 = -c[mi][ni + 2][2 * rr + 1];
                            } else {
                                r0 = c[mi][ni - 2][2 * rr];
                                r1 = c[mi][ni - 2][2 * rr + 1];
                            }
                            v0 = v0 * cs0 + r0 * sn0;
                            v1 = v1 * cs1 + r1 * sn1;
                        }
                        *reinterpret_cast<__half2*>(
                            &Qg[((size_t)h * SEQ + srow) * DQK + rem + dd]) =
                            __floats2half2_rn(v0 * QSCALE_L2E, v1 * QSCALE_L2E);
                    }
                }
            }
        } else {
            int h = col0 / 128;
            __half* Kg = p.Kp;
            if (wcol < 64) {
#pragma unroll
                for (int mi = 0; mi < 4; mi++) {
#pragma unroll
                    for (int ni = 0; ni < 4; ni++) {
                        int d = wcol + ni * 8 + 2 * t;
                        int row = row0 + wrow + mi * 16 + g;
                        *reinterpret_cast<__half2*>(
                            &Kg[((size_t)h * SEQ + row) * DQK + d]) =
                            __floats2half2_rn(c[mi][ni][0], c[mi][ni][1]);
                        *reinterpret_cast<__half2*>(
                            &Kg[((size_t)h * SEQ + row + 8) * DQK + d]) =
                            __floats2half2_rn(c[mi][ni][2], c[mi][ni][3]);
                    }
                }
            }
            __syncthreads();
            if (wcol >= 64) {
#pragma unroll
                for (int mi = 0; mi < 4; mi++) {
#pragma unroll
                    for (int ni = 0; ni < 4; ni++) {
                        int d = wcol - 64 + ni * 8 + 2 * t;
                        int sl = wrow + mi * 16 + g;
                        hsm[d * 136 + sl] = __float2half_rn(c[mi][ni][0]);
                        hsm[(d + 1) * 136 + sl] = __float2half_rn(c[mi][ni][1]);
                        hsm[d * 136 + sl + 8] = __float2half_rn(c[mi][ni][2]);
                        hsm[(d + 1) * 136 + sl + 8] = __float2half_rn(c[mi][ni][3]);
                    }
                }
            }
            __syncthreads();
            __half* Vtg = p.Vtp;
            for (int i = tid; i < 64 * 16; i += 256) {
                int d = i >> 4, sc8 = (i & 15) * 8;
                uint4 v = *reinterpret_cast<const uint4*>(&hsm[d * 136 + sc8]);
                *reinterpret_cast<uint4*>(
                    &Vtg[((size_t)(h * 64 + d)) * SEQ + row0 + sc8]) = v;
            }
        }
    });
}

// ---------------- fused norms + rope + K-rope broadcast ----------------
__global__ __launch_bounds__(256) void norm_rope(
    const __half* __restrict__ qa0, const __half* __restrict__ qa1,
    const float* __restrict__ qw,
    const __half* __restrict__ ckv0, const __half* __restrict__ ckv1,
    const float* __restrict__ kvw,
    const float* __restrict__ cosb, const float* __restrict__ sinb,
    __half* __restrict__ qan, __half* __restrict__ ckvn,
    __half* __restrict__ Kp) {
    int s = blockIdx.x;
    int tid = threadIdx.x;
    int lane = tid & 31, wid = tid >> 5;
    __shared__ float warp_s[8];
    __shared__ float snorm;
    __shared__ float kp[RD];

    float v[3];
    float ss = 0.f;
#pragma unroll
    for (int i = 0; i < 3; i++) {
        int c = tid + i * 256;
        v[i] = __half2float(qa0[(size_t)s * QA_DIM + c])
             + __half2float(qa1[(size_t)s * QA_DIM + c]);
        ss += v[i] * v[i];
    }
    for (int off = 16; off > 0; off >>= 1) ss += __shfl_down_sync(0xffffffffu, ss, off);
    if (lane == 0) warp_s[wid] = ss;
    __syncthreads();
    if (tid == 0) {
        float tt = 0.f;
#pragma unroll
        for (int i = 0; i < 8; i++) tt += warp_s[i];
        snorm = rsqrtf(tt / (float)QA_DIM + EPSV);
    }
    __syncthreads();
    float rr = snorm;
#pragma unroll
    for (int i = 0; i < 3; i++) {
        int c = tid + i * 256;
        qan[(size_t)s * QA_DIM + c] = __float2half_rn(v[i] * rr * qw[c]);
    }
    __syncthreads();

    float w = __half2float(ckv0[(size_t)s * KVA_DIM + tid])
            + __half2float(ckv1[(size_t)s * KVA_DIM + tid]);
    float ss2 = w * w;
    for (int off = 16; off > 0; off >>= 1) ss2 += __shfl_down_sync(0xffffffffu, ss2, off);
    if (lane == 0) warp_s[wid] = ss2;
    __syncthreads();
    if (tid == 0) {
        float tt = 0.f;
#pragma unroll
        for (int i = 0; i < 8; i++) tt += warp_s[i];
        snorm = rsqrtf(tt / (float)CKV_DIM + EPSV);
    }
    if (tid < RD) {
        size_t base = (size_t)s * KVA_DIM + CKV_DIM;
        float x = __half2float(ckv0[base + tid]) + __half2float(ckv1[base + tid]);
        int pp = (tid < 16) ? tid + 16 : tid - 16;
        float xr = __half2float(ckv0[base + pp]) + __half2float(ckv1[base + pp]);
        float rot = (tid < 16) ? -xr : xr;
        kp[tid] = x * cosb[(size_t)s * RD + tid]
                + rot * sinb[(size_t)s * RD + tid];
    }
    __syncthreads();
    ckvn[(size_t)s * CKV_DIM + tid] = __float2half_rn(w * snorm * kvw[tid]);
    for (int i = tid; i < NH * RD; i += 256) {
        int h = i >> 5, d = i & 31;
        Kp[((size_t)h * SEQ + s) * DQK + 64 + d] = __float2half_rn(kp[d]);
    }
}

// ===== FP16 flash attention: 256x64, 3-stage, Q frags hoisted, P in regs ====
#define FQS 104
#define FPS_V 72
#define FQS_H (256*FQS)
#define FKS_H (64*FQS)
#define FVS_H (64*FPS_V)
#define FLASH6_SMEM_BYTES ((FQS_H + 3*FKS_H + 3*FVS_H) * 2)   // 120832

__device__ __forceinline__ void flash_loadKV(const __half* __restrict__ Kh,
                                             const __half* __restrict__ Vth,
                                             int k0g, uint32_t ks_u, uint32_t vs_u,
                                             int tid) {
#pragma unroll
    for (int i = 0; i < 3; i++) {
        int idx = tid + i * 256;
        int r = idx / 12, cc = (idx % 12) * 8;
        cp16(ks_u + (uint32_t)((r * FQS + cc) * 2),
             Kh + (size_t)(k0g + r) * DQK + cc, true);
    }
#pragma unroll
    for (int i = 0; i < 2; i++) {
        int idx = tid + i * 256;
        int r = idx >> 3, cc = (idx & 7) * 8;
        cp16(vs_u + (uint32_t)((r * FPS_V + cc) * 2),
             Vth + (size_t)r * SEQ + k0g + cc, true);
    }
}

__global__ __launch_bounds__(256, 1) void flash6(const __half* __restrict__ Q,
                                                 const __half* __restrict__ K,
                                                 const __half* __restrict__ Vt,
                                                 __half* __restrict__ O) {
    extern __shared__ __half smh[];
    __half* Qs = smh;
    __half* Ks = Qs + FQS_H;
    __half* Vs = Ks + 3 * FKS_H;
    uint32_t ks_u = (uint32_t)__cvta_generic_to_shared(Ks);
    uint32_t vs_u = (uint32_t)__cvta_generic_to_shared(Vs);
    uint32_t qs_u = (uint32_t)__cvta_generic_to_shared(Qs);

    int h = blockIdx.y;
    int qt = (int)gridDim.x - 1 - (int)blockIdx.x;
    int q0 = qt * 256;
    int tid = threadIdx.x, warp = tid >> 5, lane = tid & 31;
    int g = lane >> 2, t = lane & 3;
    int wrb = warp * 32;
    int wr = wrb + g;
    int arow = lane & 15;
    int acol = (lane >> 4) * 8;
    int brow = ((lane >> 4) & 1) * 8 + (lane & 7);
    int bcol = ((lane >> 3) & 1) * 8;
    const __half* Qh = Q + (size_t)h * SEQ * DQK;
    const __half* Kh = K + (size_t)h * SEQ * DQK;
    const __half* Vth = Vt + (size_t)h * DV * SEQ;

#pragma unroll
    for (int i = 0; i < 12; i++) {
        int idx = tid + i * 256;
        int r = idx / 12, cc = (idx % 12) * 8;
        cp16(qs_u + (uint32_t)((r * FQS + cc) * 2),
             Qh + (size_t)(q0 + r) * DQK + cc, true);
    }

    float m0[2], m1[2], l0[2], l1[2];
#pragma unroll
    for (int mi = 0; mi < 2; mi++) {
        m0[mi] = -1e30f; m1[mi] = -1e30f; l0[mi] = 0.f; l1[mi] = 0.f;
    }
    float o[2][8][4];
#pragma unroll
    for (int mi = 0; mi < 2; mi++)
#pragma unroll
        for (int ni = 0; ni < 8; ni++)
#pragma unroll
            for (int r = 0; r < 4; r++) o[mi][ni][r] = 0.f;

    uint32_t qa[2][6][4];

    int nkt = 4 * qt + 4;
    flash_loadKV(Kh, Vth, 0, ks_u, vs_u, tid);
    cp_commit();
    if (1 < nkt) flash_loadKV(Kh, Vth, 64, ks_u + (uint32_t)(FKS_H * 2),
                              vs_u + (uint32_t)(FVS_H * 2), tid);
    cp_commit();

    int s_cur = 0, s_next = 2;
    for (int kt = 0; kt < nkt; kt++) {
        cp_wait<1>();
        __syncthreads();
        if (kt == 0) {
#pragma unroll
            for (int mi = 0; mi < 2; mi++)
#pragma unroll
                for (int ks = 0; ks < 6; ks++)
                    LDSM4(qa[mi][ks],
                          qs_u + (uint32_t)(((wrb + mi * 16 + arow) * FQS
                                             + ks * 16 + acol) * 2));
        }
        if (kt + 2 < nkt)
            flash_loadKV(Kh, Vth, (kt + 2) * 64,
                         ks_u + (uint32_t)(s_next * FKS_H * 2),
                         vs_u + (uint32_t)(s_next * FVS_H * 2), tid);
        cp_commit();

        uint32_t kBase = ks_u + (uint32_t)(s_cur * FKS_H * 2);
        uint32_t vBase = vs_u + (uint32_t)(s_cur * FVS_H * 2);

        float s[2][8][4];
#pragma unroll
        for (int mi = 0; mi < 2; mi++)
#pragma unroll
            for (int ni = 0; ni < 8; ni++)
#pragma unroll
                for (int r = 0; r < 4; r++) s[mi][ni][r] = 0.f;

#pragma unroll
        for (int ks = 0; ks < 6; ks++) {
            uint32_t kb[4][4];
#pragma unroll
            for (int nip = 0; nip < 4; nip++)
                LDSM4(kb[nip], kBase + (uint32_t)(((nip * 16 + brow) * FQS
                                                   + ks * 16 + bcol) * 2));
#pragma unroll
            for (int ni = 0; ni < 8; ni++) {
                MMA_F16(s[0][ni], qa[0][ks], (&kb[ni >> 1][2 * (ni & 1)]));
                MMA_F16(s[1][ni], qa[1][ks], (&kb[ni >> 1][2 * (ni & 1)]));
            }
        }

        int k0g = kt * 64;
        if (k0g + 63 > q0) {
#pragma unroll
            for (int mi = 0; mi < 2; mi++) {
                int rg = q0 + wr + mi * 16;
#pragma unroll
                for (int ni = 0; ni < 8; ni++) {
                    int col = k0g + ni * 8 + 2 * t;
                    if (col > rg)         s[mi][ni][0] = -1e30f;
                    if (col + 1 > rg)     s[mi][ni][1] = -1e30f;
                    if (col > rg + 8)     s[mi][ni][2] = -1e30f;
                    if (col + 1 > rg + 8) s[mi][ni][3] = -1e30f;
                }
            }
        }

        uint32_t ph[2][4][4];
#pragma unroll
        for (int mi = 0; mi < 2; mi++) {
            float mx0 = -1e30f, mx1 = -1e30f;
#pragma unroll
            for (int ni = 0; ni < 8; ni++) {
                mx0 = fmaxf(mx0, fmaxf(s[mi][ni][0], s[mi][ni][1]));
                mx1 = fmaxf(mx1, fmaxf(s[mi][ni][2], s[mi][ni][3]));
            }
            mx0 = fmaxf(mx0, __shfl_xor_sync(0xffffffffu, mx0, 1));
            mx0 = fmaxf(mx0, __shfl_xor_sync(0xffffffffu, mx0, 2));
            mx1 = fmaxf(mx1, __shfl_xor_sync(0xffffffffu, mx1, 1));
            mx1 = fmaxf(mx1, __shfl_xor_sync(0xffffffffu, mx1, 2));

            float mn0 = fmaxf(m0[mi], mx0), mn1 = fmaxf(m1[mi], mx1);
            float al0 = ex2f(m0[mi] - mn0), al1 = ex2f(m1[mi] - mn1);
            m0[mi] = mn0; m1[mi] = mn1;
            l0[mi] *= al0; l1[mi] *= al1;

            float sum0 = 0.f, sum1 = 0.f;
#pragma unroll
            for (int ni = 0; ni < 8; ni++) {
                float p0 = ex2f(s[mi][ni][0] - mn0);
                float p1 = ex2f(s[mi][ni][1] - mn0);
                float p2 = ex2f(s[mi][ni][2] - mn1);
                float p3 = ex2f(s[mi][ni][3] - mn1);
                sum0 += p0 + p1;
                sum1 += p2 + p3;
                int ks = ni >> 1, half8 = ni & 1;
                ph[mi][ks][2 * half8]     = packh2(p0, p1);
                ph[mi][ks][2 * half8 + 1] = packh2(p2, p3);
                o[mi][ni][0] *= al0; o[mi][ni][1] *= al0;
                o[mi][ni][2] *= al1; o[mi][ni][3] *= al1;
            }
            sum0 += __shfl_xor_sync(0xffffffffu, sum0, 1);
            sum0 += __shfl_xor_sync(0xffffffffu, sum0, 2);
            sum1 += __shfl_xor_sync(0xffffffffu, sum1, 1);
            sum1 += __shfl_xor_sync(0xffffffffu, sum1, 2);
            l0[mi] += sum0; l1[mi] += sum1;
        }

#pragma unroll
        for (int ks = 0; ks < 4; ks++) {
            uint32_t vb[4][4];
#pragma unroll
            for (int nip = 0; nip < 4; nip++)
                LDSM4(vb[nip], vBase + (uint32_t)(((nip * 16 + brow) * FPS_V
                                                   + ks * 16 + bcol) * 2));
#pragma unroll
            for (int ni = 0; ni < 8; ni++) {
                MMA_F16(o[0][ni], ph[0][ks], (&vb[ni >> 1][2 * (ni & 1)]));
                MMA_F16(o[1][ni], ph[1][ks], (&vb[ni >> 1][2 * (ni & 1)]));
            }
        }
        s_cur = (s_cur == 2) ? 0 : s_cur + 1;
        s_next = (s_next == 2) ? 0 : s_next + 1;
        __syncthreads();
    }

#pragma unroll
    for (int mi = 0; mi < 2; mi++) {
        float inv0 = 1.f / l0[mi], inv1 = 1.f / l1[mi];
        int gr = q0 + wr + mi * 16;
#pragma unroll
        for (int ni = 0; ni < 8; ni++) {
            int col = h * DV + ni * 8 + 2 * t;
            *reinterpret_cast<__half2*>(&O[(size_t)gr * (NH * DV) + col]) =
                __floats2half2_rn(o[mi][ni][0] * inv0, o[mi][ni][1] * inv0);
            *reinterpret_cast<__half2*>(&O[(size_t)(gr + 8) * (NH * DV) + col]) =
                __floats2half2_rn(o[mi][ni][2] * inv1, o[mi][ni][3] * inv1);
        }
    }
}

// ---------------- split-K final add ----------------
__global__ __launch_bounds__(256) void add_kernel(float* __restrict__ out,
                                                  const float* __restrict__ o1) {
    int i = (blockIdx.x * 256 + threadIdx.x) * 4;
    float4 a = *reinterpret_cast<float4*>(out + i);
    float4 b = *reinterpret_cast<const float4*>(o1 + i);
    a.x += b.x; a.y += b.y; a.z += b.z; a.w += b.w;
    *reinterpret_cast<float4*>(out + i) = a;
}

// ---------------- launch ----------------
extern "C" void kernel_launch(void* const* d_in, const int* in_sizes, int n_in,
                              void* d_out, int out_size) {
    const float* hidden   = (const float*)d_in[0];
    const float* cosb     = (const float*)d_in[1];
    const float* sinb     = (const float*)d_in[2];
    const float* wq_a     = (const float*)d_in[3];
    const float* q_a_ln_w = (const float*)d_in[4];
    const float* wq_b     = (const float*)d_in[5];
    const float* wkv_a    = (const float*)d_in[6];
    const float* kv_a_ln  = (const float*)d_in[7];
    const float* wkv_b    = (const float*)d_in[8];
    const float* wo       = (const float*)d_in[9];
    float* out = (float*)d_out;

    float *o1;
    __half *qa0, *qa1, *ckv0, *ckv1;
    __half *hidh, *wqaT, *wkvaT, *wqbT, *wkvbT, *woT, *qan, *ckvn, *Qp, *Kp, *Vt, *attn;
    cudaGetSymbolAddress((void**)&qa0,  g_qa0);
    cudaGetSymbolAddress((void**)&qa1,  g_qa1);
    cudaGetSymbolAddress((void**)&ckv0, g_ckv0);
    cudaGetSymbolAddress((void**)&ckv1, g_ckv1);
    cudaGetSymbolAddress((void**)&o1,   g_o1);
    cudaGetSymbolAddress((void**)&hidh, g_hidh);
    cudaGetSymbolAddress((void**)&wqaT, g_wqaT);
    cudaGetSymbolAddress((void**)&wkvaT,g_wkvaT);
    cudaGetSymbolAddress((void**)&wqbT, g_wqbT);
    cudaGetSymbolAddress((void**)&wkvbT,g_wkvbT);
    cudaGetSymbolAddress((void**)&woT,  g_woT);
    cudaGetSymbolAddress((void**)&qan,  g_qan);
    cudaGetSymbolAddress((void**)&ckvn, g_ckvn);
    cudaGetSymbolAddress((void**)&Qp,   g_Q);
    cudaGetSymbolAddress((void**)&Kp,   g_K);
    cudaGetSymbolAddress((void**)&Vt,   g_Vt);
    cudaGetSymbolAddress((void**)&attn, g_attn);

    cudaFuncSetAttribute(hgemm4, cudaFuncAttributeMaxDynamicSharedMemorySize,
                         HG_SMEM_BYTES);
    cudaFuncSetAttribute(hgemm_fused, cudaFuncAttributeMaxDynamicSharedMemorySize,
                         HG_SMEM_BYTES);
    cudaFuncSetAttribute(flash6, cudaFuncAttributeMaxDynamicSharedMemorySize,
                         FLASH6_SMEM_BYTES);

    dim3 blk(256);
    dim3 blk4(128);
    const int KH = HID / 2;   // 1280

    // 1) convert
    {
        CV6 cp;
        const float* srcs[6] = { wq_a, wkv_a, wq_b, wkv_b, wo, hidden };
        __half* dsts[6] = { wqaT, wkvaT, wqbT, wkvbT, woT, hidh };
        int Ks[6] = { HID, HID, QA_DIM, CKV_DIM, NH*DV, SEQ*HID };
        int Ns[6] = { QA_DIM, KVA_DIM, QB_DIM, KVB_DIM, OUT_DIM, 0 };
        int acc = 0;
        for (int i = 0; i < 6; i++) {
            cp.src[i] = srcs[i]; cp.dst[i] = dsts[i];
            cp.K[i] = Ks[i]; cp.N[i] = Ns[i];
            cp.bstart[i] = acc;
            if (i < 5) {
                cp.trans[i] = 1;
                cp.nbx[i] = (Ns[i] + 63) / 64;
                acc += (Ks[i] / 64) * cp.nbx[i];
            } else {
                cp.trans[i] = 0;
                cp.nbx[i] = 1;
                acc += Ks[i] / 4096;
            }
        }
        cp.bstart[6] = acc;
        convtrans<<<acc, blk>>>(cp);
    }

    // 2) merged split-K down-projections (half out, 4-warp kernel)
    {
        GP4 p;
        p.nprob = 4;
        p.cosp = cosb; p.sinp = sinb; p.Qp = Qp; p.Kp = Kp; p.Vtp = Vt;
        p.A[0] = hidh;      p.B[0] = wqaT;       p.C[0] = (float*)qa0;
        p.N[0] = QA_DIM;  p.K[0] = KH; p.lda[0] = HID; p.ldb[0] = HID;
        p.nbx[0] = QA_DIM / 128; p.mode[0] = 1;
        p.A[1] = hidh + KH; p.B[1] = wqaT + KH;  p.C[1] = (float*)qa1;
        p.N[1] = QA_DIM;  p.K[1] = KH; p.lda[1] = HID; p.ldb[1] = HID;
        p.nbx[1] = QA_DIM / 128; p.mode[1] = 1;
        p.A[2] = hidh;      p.B[2] = wkvaT;      p.C[2] = (float*)ckv0;
        p.N[2] = KVA_DIM; p.K[2] = KH; p.lda[2] = HID; p.ldb[2] = HID;
        p.nbx[2] = (KVA_DIM + 127) / 128; p.mode[2] = 1;
        p.A[3] = hidh + KH; p.B[3] = wkvaT + KH; p.C[3] = (float*)ckv1;
        p.N[3] = KVA_DIM; p.K[3] = KH; p.lda[3] = HID; p.ldb[3] = HID;
        p.nbx[3] = (KVA_DIM + 127) / 128; p.mode[3] = 1;
        int nb0 = p.nbx[0] * (SEQ / 128);
        int nb2 = p.nbx[2] * (SEQ / 128);
        p.bstart[0] = 0; p.bstart[1] = nb0;
        p.bstart[2] = 2 * nb0; p.bstart[3] = 2 * nb0 + nb2;
        hgemm4<<<2 * nb0 + 2 * nb2, blk4, HG_SMEM_BYTES>>>(p);
    }
    // 3) fused norms + rope (+ K rope broadcast)
    norm_rope<<<SEQ, 256>>>(qa0, qa1, q_a_ln_w, ckv0, ckv1, kv_a_ln,
                            cosb, sinb, qan, ckvn, Kp);
    // 4) merged up-projections, FUSED epilogues (Q rope / K / Vt)
    {
        GP4 p;
        p.nprob = 2;
        p.cosp = cosb; p.sinp = sinb; p.Qp = Qp; p.Kp = Kp; p.Vtp = Vt;
        p.A[0] = qan;  p.B[0] = wqbT;  p.C[0] = nullptr;
        p.N[0] = QB_DIM;  p.K[0] = QA_DIM; p.lda[0] = QA_DIM; p.ldb[0] = QA_DIM;
        p.nbx[0] = QB_DIM / 128; p.mode[0] = 2;
        p.A[1] = ckvn; p.B[1] = wkvbT; p.C[1] = nullptr;
        p.N[1] = KVB_DIM; p.K[1] = CKV_DIM; p.lda[1] = CKV_DIM; p.ldb[1] = CKV_DIM;
        p.nbx[1] = KVB_DIM / 128; p.mode[1] = 3;
        p.A[2] = p.A[0]; p.B[2] = p.B[0]; p.C[2] = p.C[0];
        p.N[2] = p.N[0]; p.K[2] = p.K[0]; p.lda[2] = p.lda[0]; p.ldb[2] = p.ldb[0];
        p.nbx[2] = 1; p.mode[2] = 2;
        p.A[3] = p.A[0]; p.B[3] = p.B[0]; p.C[3] = p.C[0];
        p.N[3] = p.N[0]; p.K[3] = p.K[0]; p.lda[3] = p.lda[0]; p.ldb[3] = p.ldb[0];
        p.nbx[3] = 1; p.mode[3] = 2;
        int nb0 = p.nbx[0] * (SEQ / 128);
        int nb1 = p.nbx[1] * (SEQ / 128);
        p.bstart[0] = 0; p.bstart[1] = nb0;
        p.bstart[2] = nb0 + nb1; p.bstart[3] = nb0 + nb1;
        hgemm_fused<<<nb0 + nb1, blk, HG_SMEM_BYTES>>>(p);
    }
    // 5) flash attention
    flash6<<<dim3(SEQ / 256, NH), blk, FLASH6_SMEM_BYTES>>>(Qp, Kp, Vt, attn);
    // 6) attn @ wo, split-K x2 (fp32 out, 4-warp kernel)
    {
        const int KW = (NH * DV) / 2;   // 1280
        GP4 p;
        p.nprob = 2;
        p.cosp = cosb; p.sinp = sinb; p.Qp = Qp; p.Kp = Kp; p.Vtp = Vt;
        p.A[0] = attn;      p.B[0] = woT;       p.C[0] = out;
        p.N[0] = OUT_DIM; p.K[0] = KW; p.lda[0] = NH * DV; p.ldb[0] = NH * DV;
        p.nbx[0] = OUT_DIM / 128; p.mode[0] = 0;
        p.A[1] = attn + KW; p.B[1] = woT + KW;  p.C[1] = o1;
        p.N[1] = OUT_DIM; p.K[1] = KW; p.lda[1] = NH * DV; p.ldb[1] = NH * DV;
        p.nbx[1] = OUT_DIM / 128; p.mode[1] = 0;
        p.A[2] = p.A[0]; p.B[2] = p.B[0]; p.C[2] = p.C[0];
        p.N[2] = p.N[0]; p.K[2] = p.K[0]; p.lda[2] = p.lda[0]; p.ldb[2] = p.ldb[0];
        p.nbx[2] = 1; p.mode[2] = 0;
        p.A[3] = p.A[0]; p.B[3] = p.B[0]; p.C[3] = p.C[0];
        p.N[3] = p.N[0]; p.K[3] = p.K[0]; p.lda[3] = p.lda[0]; p.ldb[3] = p.ldb[0];
        p.nbx[3] = 1; p.mode[3] = 0;
        int nb = p.nbx[0] * (SEQ / 128);
        p.bstart[0] = 0; p.bstart[1] = nb;
        p.bstart[2] = 2 * nb; p.bstart[3] = 2 * nb;
        hgemm4<<<2 * nb, blk4, HG_SMEM_BYTES>>>(p);
    }
    // 7) out += o1
    add_kernel<<<(SEQ * OUT_DIM) / (256 * 4), blk>>>(out, o1);
}

// round 16
// speedup vs baseline: 1.0273x; 1.0273x over previous
#include <cuda_runtime.h>
#include <cuda_fp16.h>
#include <math.h>
#include <stdint.h>

// ---------------- problem constants ----------------
#define SEQ 2048
#define HID 2560
#define NH 40
#define DQK 96
#define DV 64
#define RD 32
#define QA_DIM 768
#define KVA_DIM 288
#define CKV_DIM 256
#define QB_DIM (NH*DQK)         // 3840
#define KVB_DIM (NH*(64+DV))    // 5120
#define OUT_DIM 2560
#define EPSV 1e-6f
#define QSCALE_L2E 0.14724602233502312f   // 96^-0.5 * log2(e)

// ---------------- scratch ----------------
__device__ __half g_qa0 [SEQ*QA_DIM];
__device__ __half g_qa1 [SEQ*QA_DIM];
__device__ __half g_ckv0[SEQ*KVA_DIM];
__device__ __half g_ckv1[SEQ*KVA_DIM];
__device__ float  g_o1  [SEQ*OUT_DIM];
__device__ __half g_hidh[SEQ*HID];
__device__ __half g_wqaT[QA_DIM*HID];
__device__ __half g_wkvaT[KVA_DIM*HID];
__device__ __half g_wqbT[QB_DIM*QA_DIM];
__device__ __half g_wkvbT[KVB_DIM*CKV_DIM];
__device__ __half g_woT [OUT_DIM*(NH*DV)];
__device__ __half g_qan [SEQ*QA_DIM];
__device__ __half g_ckvn[SEQ*CKV_DIM];
__device__ __half g_Q   [NH*SEQ*DQK];
__device__ __half g_K   [NH*SEQ*DQK];
__device__ __half g_Vt  [NH*DV*SEQ];
__device__ __half g_attn[SEQ*NH*DV];

// ---------------- helpers ----------------
__device__ __forceinline__ float ex2f(float x) {
    float r;
    asm("ex2.approx.ftz.f32 %0, %1;" : "=f"(r) : "f"(x));
    return r;
}
__device__ __forceinline__ void cp16(uint32_t dst, const void* src, bool pred) {
    int sz = pred ? 16 : 0;
    asm volatile("cp.async.cg.shared.global [%0], [%1], 16, %2;\n"
                 :: "r"(dst), "l"(src), "r"(sz));
}
__device__ __forceinline__ void cp_commit() {
    asm volatile("cp.async.commit_group;\n");
}
template <int N>
__device__ __forceinline__ void cp_wait() {
    asm volatile("cp.async.wait_group %0;\n" :: "n"(N));
}

#define MMA_F16(c, a, b) \
    asm volatile("mma.sync.aligned.m16n8k16.row.col.f32.f16.f16.f32 " \
                 "{%0,%1,%2,%3},{%4,%5,%6,%7},{%8,%9},{%0,%1,%2,%3};" \
                 : "+f"(c[0]), "+f"(c[1]), "+f"(c[2]), "+f"(c[3]) \
                 : "r"(a[0]), "r"(a[1]), "r"(a[2]), "r"(a[3]), \
                   "r"(b[0]), "r"(b[1]))

#define LDSM4(r, addr) \
    asm volatile("ldmatrix.sync.aligned.m8n8.x4.shared.b16 {%0,%1,%2,%3}, [%4];" \
                 : "=r"((r)[0]), "=r"((r)[1]), "=r"((r)[2]), "=r"((r)[3]) \
                 : "r"(addr))

__device__ __forceinline__ uint32_t packh2(float a, float b) {
    __half2 h = __floats2half2_rn(a, b);
    return *reinterpret_cast<uint32_t*>(&h);
}

// ================= convert / transpose pass =================
struct CV6 {
    const float* src[6];
    __half* dst[6];
    int K[6], N[6];
    int nbx[6];
    int bstart[7];
    int trans[6];
};
__global__ __launch_bounds__(256) void convtrans(CV6 p) {
    __shared__ __half sm[64 * 72];
    int bid = blockIdx.x;
    int pi = 0;
#pragma unroll
    for (int i = 1; i < 6; i++) if (bid >= p.bstart[i]) pi = i;
    int l = bid - p.bstart[pi];
    int tid = threadIdx.x;
    if (p.trans[pi]) {
        int K = p.K[pi], N = p.N[pi];
        int k0 = (l / p.nbx[pi]) * 64;
        int n0 = (l % p.nbx[pi]) * 64;
        const float* src = p.src[pi];
#pragma unroll
        for (int i = 0; i < 4; i++) {
            int idx = tid + i * 256;
            int r = idx >> 4, c4 = idx & 15;
            int n = n0 + c4 * 4;
            if (n < N) {
                float4 v = *reinterpret_cast<const float4*>(
                    &src[(size_t)(k0 + r) * N + n]);
                sm[(c4 * 4 + 0) * 72 + r] = __float2half_rn(v.x);
                sm[(c4 * 4 + 1) * 72 + r] = __float2half_rn(v.y);
                sm[(c4 * 4 + 2) * 72 + r] = __float2half_rn(v.z);
                sm[(c4 * 4 + 3) * 72 + r] = __float2half_rn(v.w);
            }
        }
        __syncthreads();
        __half* dst = p.dst[pi];
#pragma unroll
        for (int i = 0; i < 2; i++) {
            int idx = tid + i * 256;
            int rr = idx >> 3, cc = idx & 7;
            if (n0 + rr < N) {
                uint4 v = *reinterpret_cast<const uint4*>(&sm[rr * 72 + cc * 8]);
                *reinterpret_cast<uint4*>(
                    &dst[(size_t)(n0 + rr) * K + k0 + cc * 8]) = v;
            }
        }
    } else {
        const float* src = p.src[pi];
        __half* dst = p.dst[pi];
        int base = l * 4096;
#pragma unroll
        for (int i = 0; i < 4; i++) {
            int e = base + (tid + i * 256) * 4;
            float4 v = *reinterpret_cast<const float4*>(&src[e]);
            __half2 h0 = __floats2half2_rn(v.x, v.y);
            __half2 h1 = __floats2half2_rn(v.z, v.w);
            *reinterpret_cast<__half2*>(&dst[e]) = h0;
            *reinterpret_cast<__half2*>(&dst[e + 2]) = h1;
        }
    }
}

// ======= shared GEMM config (128x128x64, 3-stage, ldmatrix) ===========
#define HSTR 72
#define HBUF (128*HSTR)
#define HG_SMEM_BYTES (3*2*HBUF*2)      // 110592

struct GP4 {
    const __half* A[4];
    const __half* B[4];   // BT [N][K]
    float*        C[4];
    int N[4], K[4], lda[4], ldb[4], nbx[4], bstart[4];
    int mode[4];          // 0=fp32 out, 1=half out; fused: 2=Q, 3=KV
    int nprob;
    const float* cosp;
    const float* sinp;
    __half* Qp;
    __half* Kp;
    __half* Vtp;
};

template <typename EPI>
__device__ __forceinline__ void hgemm_body(const GP4& p, EPI epi) {
    extern __shared__ __half hsm[];
    uint32_t sm_u = (uint32_t)__cvta_generic_to_shared(hsm);

    int bid = blockIdx.x;
    int pi = 0;
#pragma unroll
    for (int i = 1; i < 4; i++)
        if (i < p.nprob && bid >= p.bstart[i]) pi = i;
    const __half* A = p.A[pi];
    const __half* B = p.B[pi];
    int N = p.N[pi], K = p.K[pi], lda = p.lda[pi], ldb = p.ldb[pi];
    int l = bid - p.bstart[pi];
    int row0 = (l / p.nbx[pi]) * 128;
    int col0 = (l % p.nbx[pi]) * 128;

    int tid = threadIdx.x;
    int warp = tid >> 5, lane = tid & 31;
    int wrow = (warp >> 2) * 64;
    int wcol = (warp & 3) * 32;
    int arow = lane & 15;
    int acol = (lane >> 4) * 8;
    int brow = ((lane >> 4) & 1) * 8 + (lane & 7);
    int bcol = ((lane >> 3) & 1) * 8;

    float c[4][4][4];
#pragma unroll
    for (int mi = 0; mi < 4; mi++)
#pragma unroll
        for (int ni = 0; ni < 4; ni++)
#pragma unroll
            for (int r = 0; r < 4; r++) c[mi][ni][r] = 0.f;

    int kt_total = K / 64;

    auto load_tile = [&](int kt, int stg) {
        int k0 = kt * 64;
        uint32_t aD = sm_u + (uint32_t)(stg * 2 * HBUF * 2);
        uint32_t bD = aD + (uint32_t)(HBUF * 2);
#pragma unroll
        for (int i = 0; i < 4; i++) {
            int idx = tid + i * 256;
            int r = idx >> 3, cc = (idx & 7) * 8;
            cp16(aD + (uint32_t)((r * HSTR + cc) * 2),
                 A + (size_t)(row0 + r) * lda + k0 + cc, true);
        }
#pragma unroll
        for (int i = 0; i < 4; i++) {
            int idx = tid + i * 256;
            int r = idx >> 3, cc = (idx & 7) * 8;
            bool pr = (col0 + r) < N;
            const __half* src = pr ? (B + (size_t)(col0 + r) * ldb + k0 + cc) : B;
            cp16(bD + (uint32_t)((r * HSTR + cc) * 2), src, pr);
        }
    };

    load_tile(0, 0); cp_commit();
    load_tile(1, 1); cp_commit();

    int s_cur = 0, s_next = 2;
    for (int kt = 0; kt < kt_total; kt++) {
        cp_wait<1>();
        __syncthreads();
        if (kt + 2 < kt_total) load_tile(kt + 2, s_next);
        cp_commit();

        uint32_t aBase = sm_u + (uint32_t)(s_cur * 2 * HBUF * 2);
        uint32_t bBase = aBase + (uint32_t)(HBUF * 2);
#pragma unroll
        for (int k0 = 0; k0 < 64; k0 += 16) {
            uint32_t a[4][4], bb[2][4];
#pragma unroll
            for (int mi = 0; mi < 4; mi++)
                LDSM4(a[mi], aBase + (uint32_t)(((wrow + mi * 16 + arow) * HSTR
                                                 + k0 + acol) * 2));
#pragma unroll
            for (int nip = 0; nip < 2; nip++)
                LDSM4(bb[nip], bBase + (uint32_t)(((wcol + nip * 16 + brow) * HSTR
                                                   + k0 + bcol) * 2));
#pragma unroll
            for (int mi = 0; mi < 4; mi++)
#pragma unroll
                for (int ni = 0; ni < 4; ni++)
                    MMA_F16(c[mi][ni], a[mi], (&bb[ni >> 1][2 * (ni & 1)]));
        }
        s_cur = (s_cur == 2) ? 0 : s_cur + 1;
        s_next = (s_next == 2) ? 0 : s_next + 1;
    }
    epi(pi, row0, col0, N, c);
}

// ---- plain GEMM (fp32 or half epilogue) ----
__global__ __launch_bounds__(256, 2) void hgemm_plain(GP4 p) {
    int tid = threadIdx.x;
    int warp = tid >> 5, lane = tid & 31;
    int g = lane >> 2, t = lane & 3;
    int wrow = (warp >> 2) * 64;
    int wcol = (warp & 3) * 32;
    hgemm_body(p, [&](int pi, int row0, int col0, int N, float c[4][4][4]) {
        if (p.mode[pi] == 1) {
            __half* Ch = reinterpret_cast<__half*>(p.C[pi]);
#pragma unroll
            for (int mi = 0; mi < 4; mi++) {
#pragma unroll
                for (int ni = 0; ni < 4; ni++) {
                    int row = row0 + wrow + mi * 16 + g;
                    int col = col0 + wcol + ni * 8 + 2 * t;
                    if (col < N) {
                        *reinterpret_cast<__half2*>(&Ch[(size_t)row * N + col]) =
                            __floats2half2_rn(c[mi][ni][0], c[mi][ni][1]);
                        *reinterpret_cast<__half2*>(&Ch[(size_t)(row + 8) * N + col]) =
                            __floats2half2_rn(c[mi][ni][2], c[mi][ni][3]);
                    }
                }
            }
        } else {
            float* C = p.C[pi];
#pragma unroll
            for (int mi = 0; mi < 4; mi++) {
#pragma unroll
                for (int ni = 0; ni < 4; ni++) {
                    int row = row0 + wrow + mi * 16 + g;
                    int col = col0 + wcol + ni * 8 + 2 * t;
                    if (col < N) {
                        float2 v0 = make_float2(c[mi][ni][0], c[mi][ni][1]);
                        float2 v1 = make_float2(c[mi][ni][2], c[mi][ni][3]);
                        *reinterpret_cast<float2*>(&C[(size_t)row * N + col]) = v0;
                        *reinterpret_cast<float2*>(&C[(size_t)(row + 8) * N + col]) = v1;
                    }
                }
            }
        }
    });
}

// ---- fused GEMM (Q-rope / K+Vt epilogues) ----
__global__ __launch_bounds__(256, 2) void hgemm_fused(GP4 p) {
    extern __shared__ __half hsm[];
    int tid = threadIdx.x;
    int warp = tid >> 5, lane = tid & 31;
    int g = lane >> 2, t = lane & 3;
    int wrow = (warp >> 2) * 64;
    int wcol = (warp & 3) * 32;
    hgemm_body(p, [&](int pi, int row0, int col0, int N, float c[4][4][4]) {
        int mode = p.mode[pi];
        if (mode == 2) {
            int cb = col0 + wcol;
            int h = cb / 96;
            int rem = cb % 96;
            bool ropeBlk = (rem == 64);
            __half* Qg = p.Qp;
#pragma unroll
            for (int mi = 0; mi < 4; mi++) {
#pragma unroll
                for (int rr = 0; rr < 2; rr++) {
                    int srow = row0 + wrow + mi * 16 + g + 8 * rr;
                    const float* cosr = p.cosp + (size_t)srow * RD;
                    const float* sinr = p.sinp + (size_t)srow * RD;
#pragma unroll
                    for (int ni = 0; ni < 4; ni++) {
                        int dd = ni * 8 + 2 * t;
                        float v0 = c[mi][ni][2 * rr];
                        float v1 = c[mi][ni][2 * rr + 1];
                        if (ropeBlk) {
                            float cs0 = cosr[dd], sn0 = sinr[dd];
                            float cs1 = cosr[dd + 1], sn1 = sinr[dd + 1];
                            float r0, r1;
                            if (ni < 2) {
                                r0 = -c[mi][ni + 2][2 * rr];
                                r1 = -c[mi][ni + 2][2 * rr + 1];
                            } else {
                                r0 = c[mi][ni - 2][2 * rr];
                                r1 = c[mi][ni - 2][2 * rr + 1];
                            }
                            v0 = v0 * cs0 + r0 * sn0;
                            v1 = v1 * cs1 + r1 * sn1;
                        }
                        *reinterpret_cast<__half2*>(
                            &Qg[((size_t)h * SEQ + srow) * DQK + rem + dd]) =
                            __floats2half2_rn(v0 * QSCALE_L2E, v1 * QSCALE_L2E);
                    }
                }
            }
        } else {
            int h = col0 / 128;
            __half* Kg = p.Kp;
            if (wcol < 64) {
#pragma unroll
                for (int mi = 0; mi < 4; mi++) {
#pragma unroll
                    for (int ni = 0; ni < 4; ni++) {
                        int d = wcol + ni * 8 + 2 * t;
                        int row = row0 + wrow + mi * 16 + g;
                        *reinterpret_cast<__half2*>(
                            &Kg[((size_t)h * SEQ + row) * DQK + d]) =
                            __floats2half2_rn(c[mi][ni][0], c[mi][ni][1]);
                        *reinterpret_cast<__half2*>(
                            &Kg[((size_t)h * SEQ + row + 8) * DQK + d]) =
                            __floats2half2_rn(c[mi][ni][2], c[mi][ni][3]);
                    }
                }
            }
            __syncthreads();
            if (wcol >= 64) {
#pragma unroll
                for (int mi = 0; mi < 4; mi++) {
#pragma unroll
                    for (int ni = 0; ni < 4; ni++) {
                        int d = wcol - 64 + ni * 8 + 2 * t;
                        int sl = wrow + mi * 16 + g;
                        hsm[d * 136 + sl] = __float2half_rn(c[mi][ni][0]);
                        hsm[(d + 1) * 136 + sl] = __float2half_rn(c[mi][ni][1]);
                        hsm[d * 136 + sl + 8] = __float2half_rn(c[mi][ni][2]);
                        hsm[(d + 1) * 136 + sl + 8] = __float2half_rn(c[mi][ni][3]);
                    }
                }
            }
            __syncthreads();
            __half* Vtg = p.Vtp;
            for (int i = tid; i < 64 * 16; i += 256) {
                int d = i >> 4, sc8 = (i & 15) * 8;
                uint4 v = *reinterpret_cast<const uint4*>(&hsm[d * 136 + sc8]);
                *reinterpret_cast<uint4*>(
                    &Vtg[((size_t)(h * 64 + d)) * SEQ + row0 + sc8]) = v;
            }
        }
    });
}

// ---------------- fused norms + rope + K-rope broadcast ----------------
__global__ __launch_bounds__(256) void norm_rope(
    const __half* __restrict__ qa0, const __half* __restrict__ qa1,
    const float* __restrict__ qw,
    const __half* __restrict__ ckv0, const __half* __restrict__ ckv1,
    const float* __restrict__ kvw,
    const float* __restrict__ cosb, const float* __restrict__ sinb,
    __half* __restrict__ qan, __half* __restrict__ ckvn,
    __half* __restrict__ Kp) {
    int s = blockIdx.x;
    int tid = threadIdx.x;
    int lane = tid & 31, wid = tid >> 5;
    __shared__ float warp_s[8];
    __shared__ float snorm;
    __shared__ float kp[RD];

    float v[3];
    float ss = 0.f;
#pragma unroll
    for (int i = 0; i < 3; i++) {
        int c = tid + i * 256;
        v[i] = __half2float(qa0[(size_t)s * QA_DIM + c])
             + __half2float(qa1[(size_t)s * QA_DIM + c]);
        ss += v[i] * v[i];
    }
    for (int off = 16; off > 0; off >>= 1) ss += __shfl_down_sync(0xffffffffu, ss, off);
    if (lane == 0) warp_s[wid] = ss;
    __syncthreads();
    if (tid == 0) {
        float tt = 0.f;
#pragma unroll
        for (int i = 0; i < 8; i++) tt += warp_s[i];
        snorm = rsqrtf(tt / (float)QA_DIM + EPSV);
    }
    __syncthreads();
    float rr = snorm;
#pragma unroll
    for (int i = 0; i < 3; i++) {
        int c = tid + i * 256;
        qan[(size_t)s * QA_DIM + c] = __float2half_rn(v[i] * rr * qw[c]);
    }
    __syncthreads();

    float w = __half2float(ckv0[(size_t)s * KVA_DIM + tid])
            + __half2float(ckv1[(size_t)s * KVA_DIM + tid]);
    float ss2 = w * w;
    for (int off = 16; off > 0; off >>= 1) ss2 += __shfl_down_sync(0xffffffffu, ss2, off);
    if (lane == 0) warp_s[wid] = ss2;
    __syncthreads();
    if (tid == 0) {
        float tt = 0.f;
#pragma unroll
        for (int i = 0; i < 8; i++) tt += warp_s[i];
        snorm = rsqrtf(tt / (float)CKV_DIM + EPSV);
    }
    if (tid < RD) {
        size_t base = (size_t)s * KVA_DIM + CKV_DIM;
        float x = __half2float(ckv0[base + tid]) + __half2float(ckv1[base + tid]);
        int pp = (tid < 16) ? tid + 16 : tid - 16;
        float xr = __half2float(ckv0[base + pp]) + __half2float(ckv1[base + pp]);
        float rot = (tid < 16) ? -xr : xr;
        kp[tid] = x * cosb[(size_t)s * RD + tid]
                + rot * sinb[(size_t)s * RD + tid];
    }
    __syncthreads();
    ckvn[(size_t)s * CKV_DIM + tid] = __float2half_rn(w * snorm * kvw[tid]);
    for (int i = tid; i < NH * RD; i += 256) {
        int h = i >> 5, d = i & 31;
        Kp[((size_t)h * SEQ + s) * DQK + 64 + d] = __float2half_rn(kp[d]);
    }
}

// ===== FP16 flash attention: 256x64, 3-stage, Q frags hoisted, P in regs ====
#define FQS 104
#define FPS_V 72
#define FQS_H (256*FQS)
#define FKS_H (64*FQS)
#define FVS_H (64*FPS_V)
#define FLASH6_SMEM_BYTES ((FQS_H + 3*FKS_H + 3*FVS_H) * 2)   // 120832

__device__ __forceinline__ void flash_loadKV(const __half* __restrict__ Kh,
                                             const __half* __restrict__ Vth,
                                             int k0g, uint32_t ks_u, uint32_t vs_u,
                                             int tid) {
#pragma unroll
    for (int i = 0; i < 3; i++) {
        int idx = tid + i * 256;
        int r = idx / 12, cc = (idx % 12) * 8;
        cp16(ks_u + (uint32_t)((r * FQS + cc) * 2),
             Kh + (size_t)(k0g + r) * DQK + cc, true);
    }
#pragma unroll
    for (int i = 0; i < 2; i++) {
        int idx = tid + i * 256;
        int r = idx >> 3, cc = (idx & 7) * 8;
        cp16(vs_u + (uint32_t)((r * FPS_V + cc) * 2),
             Vth + (size_t)r * SEQ + k0g + cc, true);
    }
}

__global__ __launch_bounds__(256, 1) void flash6(const __half* __restrict__ Q,
                                                 const __half* __restrict__ K,
                                                 const __half* __restrict__ Vt,
                                                 __half* __restrict__ O) {
    extern __shared__ __half smh[];
    __half* Qs = smh;
    __half* Ks = Qs + FQS_H;
    __half* Vs = Ks + 3 * FKS_H;
    uint32_t ks_u = (uint32_t)__cvta_generic_to_shared(Ks);
    uint32_t vs_u = (uint32_t)__cvta_generic_to_shared(Vs);
    uint32_t qs_u = (uint32_t)__cvta_generic_to_shared(Qs);

    int h = blockIdx.y;
    int qt = (int)gridDim.x - 1 - (int)blockIdx.x;
    int q0 = qt * 256;
    int tid = threadIdx.x, warp = tid >> 5, lane = tid & 31;
    int g = lane >> 2, t = lane & 3;
    int wrb = warp * 32;
    int wr = wrb + g;
    int arow = lane & 15;
    int acol = (lane >> 4) * 8;
    int brow = ((lane >> 4) & 1) * 8 + (lane & 7);
    int bcol = ((lane >> 3) & 1) * 8;
    const __half* Qh = Q + (size_t)h * SEQ * DQK;
    const __half* Kh = K + (size_t)h * SEQ * DQK;
    const __half* Vth = Vt + (size_t)h * DV * SEQ;

#pragma unroll
    for (int i = 0; i < 12; i++) {
        int idx = tid + i * 256;
        int r = idx / 12, cc = (idx % 12) * 8;
        cp16(qs_u + (uint32_t)((r * FQS + cc) * 2),
             Qh + (size_t)(q0 + r) * DQK + cc, true);
    }

    float m0[2], m1[2], l0[2], l1[2];
#pragma unroll
    for (int mi = 0; mi < 2; mi++) {
        m0[mi] = -1e30f; m1[mi] = -1e30f; l0[mi] = 0.f; l1[mi] = 0.f;
    }
    float o[2][8][4];
#pragma unroll
    for (int mi = 0; mi < 2; mi++)
#pragma unroll
        for (int ni = 0; ni < 8; ni++)
#pragma unroll
            for (int r = 0; r < 4; r++) o[mi][ni][r] = 0.f;

    uint32_t qa[2][6][4];

    int nkt = 4 * qt + 4;
    flash_loadKV(Kh, Vth, 0, ks_u, vs_u, tid);
    cp_commit();
    if (1 < nkt) flash_loadKV(Kh, Vth, 64, ks_u + (uint32_t)(FKS_H * 2),
                              vs_u + (uint32_t)(FVS_H * 2), tid);
    cp_commit();

    int s_cur = 0, s_next = 2;
    for (int kt = 0; kt < nkt; kt++) {
        // Single barrier per K-tile: orders (a) completed cp.async data for
        // s_cur (after cp_wait) and (b) all warps' reads of the buffer that
        // this iteration's prefetch will overwrite (it was last read at kt-1).
        cp_wait<1>();
        __syncthreads();
        if (kt == 0) {
#pragma unroll
            for (int mi = 0; mi < 2; mi++)
#pragma unroll
                for (int ks = 0; ks < 6; ks++)
                    LDSM4(qa[mi][ks],
                          qs_u + (uint32_t)(((wrb + mi * 16 + arow) * FQS
                                             + ks * 16 + acol) * 2));
        }
        if (kt + 2 < nkt)
            flash_loadKV(Kh, Vth, (kt + 2) * 64,
                         ks_u + (uint32_t)(s_next * FKS_H * 2),
                         vs_u + (uint32_t)(s_next * FVS_H * 2), tid);
        cp_commit();

        uint32_t kBase = ks_u + (uint32_t)(s_cur * FKS_H * 2);
        uint32_t vBase = vs_u + (uint32_t)(s_cur * FVS_H * 2);

        float s[2][8][4];
#pragma unroll
        for (int mi = 0; mi < 2; mi++)
#pragma unroll
            for (int ni = 0; ni < 8; ni++)
#pragma unroll
                for (int r = 0; r < 4; r++) s[mi][ni][r] = 0.f;

#pragma unroll
        for (int ks = 0; ks < 6; ks++) {
            uint32_t kb[4][4];
#pragma unroll
            for (int nip = 0; nip < 4; nip++)
                LDSM4(kb[nip], kBase + (uint32_t)(((nip * 16 + brow) * FQS
                                                   + ks * 16 + bcol) * 2));
#pragma unroll
            for (int ni = 0; ni < 8; ni++) {
                MMA_F16(s[0][ni], qa[0][ks], (&kb[ni >> 1][2 * (ni & 1)]));
                MMA_F16(s[1][ni], qa[1][ks], (&kb[ni >> 1][2 * (ni & 1)]));
            }
        }

        int k0g = kt * 64;
        if (k0g + 63 > q0) {
#pragma unroll
            for (int mi = 0; mi < 2; mi++) {
                int rg = q0 + wr + mi * 16;
#pragma unroll
                for (int ni = 0; ni < 8; ni++) {
                    int col = k0g + ni * 8 + 2 * t;
                    if (col > rg)         s[mi][ni][0] = -1e30f;
                    if (col + 1 > rg)     s[mi][ni][1] = -1e30f;
                    if (col > rg + 8)     s[mi][ni][2] = -1e30f;
                    if (col + 1 > rg + 8) s[mi][ni][3] = -1e30f;
                }
            }
        }

        uint32_t ph[2][4][4];
#pragma unroll
        for (int mi = 0; mi < 2; mi++) {
            float mx0 = -1e30f, mx1 = -1e30f;
#pragma unroll
            for (int ni = 0; ni < 8; ni++) {
                mx0 = fmaxf(mx0, fmaxf(s[mi][ni][0], s[mi][ni][1]));
                mx1 = fmaxf(mx1, fmaxf(s[mi][ni][2], s[mi][ni][3]));
            }
            mx0 = fmaxf(mx0, __shfl_xor_sync(0xffffffffu, mx0, 1));
            mx0 = fmaxf(mx0, __shfl_xor_sync(0xffffffffu, mx0, 2));
            mx1 = fmaxf(mx1, __shfl_xor_sync(0xffffffffu, mx1, 1));
            mx1 = fmaxf(mx1, __shfl_xor_sync(0xffffffffu, mx1, 2));

            float mn0 = fmaxf(m0[mi], mx0), mn1 = fmaxf(m1[mi], mx1);
            float al0 = ex2f(m0[mi] - mn0), al1 = ex2f(m1[mi] - mn1);
            m0[mi] = mn0; m1[mi] = mn1;
            l0[mi] *= al0; l1[mi] *= al1;

            float sum0 = 0.f, sum1 = 0.f;
#pragma unroll
            for (int ni = 0; ni < 8; ni++) {
                float p0 = ex2f(s[mi][ni][0] - mn0);
                float p1 = ex2f(s[mi][ni][1] - mn0);
                float p2 = ex2f(s[mi][ni][2] - mn1);
                float p3 = ex2f(s[mi][ni][3] - mn1);
                sum0 += p0 + p1;
                sum1 += p2 + p3;
                int ks = ni >> 1, half8 = ni & 1;
                ph[mi][ks][2 * half8]     = packh2(p0, p1);
                ph[mi][ks][2 * half8 + 1] = packh2(p2, p3);
                o[mi][ni][0] *= al0; o[mi][ni][1] *= al0;
                o[mi][ni][2] *= al1; o[mi][ni][3] *= al1;
            }
            sum0 += __shfl_xor_sync(0xffffffffu, sum0, 1);
            sum0 += __shfl_xor_sync(0xffffffffu, sum0, 2);
            sum1 += __shfl_xor_sync(0xffffffffu, sum1, 1);
            sum1 += __shfl_xor_sync(0xffffffffu, sum1, 2);
            l0[mi] += sum0; l1[mi] += sum1;
        }

#pragma unroll
        for (int ks = 0; ks < 4; ks++) {
            uint32_t vb[4][4];
#pragma unroll
            for (int nip = 0; nip < 4; nip++)
                LDSM4(vb[nip], vBase + (uint32_t)(((nip * 16 + brow) * FPS_V
                                                   + ks * 16 + bcol) * 2));
#pragma unroll
            for (int ni = 0; ni < 8; ni++) {
                MMA_F16(o[0][ni], ph[0][ks], (&vb[ni >> 1][2 * (ni & 1)]));
                MMA_F16(o[1][ni], ph[1][ks], (&vb[ni >> 1][2 * (ni & 1)]));
            }
        }
        s_cur = (s_cur == 2) ? 0 : s_cur + 1;
        s_next = (s_next == 2) ? 0 : s_next + 1;
        // NOTE: no end-of-loop __syncthreads — next iteration's top barrier
        // (before its prefetch) provides the required WAR ordering.
    }

#pragma unroll
    for (int mi = 0; mi < 2; mi++) {
        float inv0 = 1.f / l0[mi], inv1 = 1.f / l1[mi];
        int gr = q0 + wr + mi * 16;
#pragma unroll
        for (int ni = 0; ni < 8; ni++) {
            int col = h * DV + ni * 8 + 2 * t;
            *reinterpret_cast<__half2*>(&O[(size_t)gr * (NH * DV) + col]) =
                __floats2half2_rn(o[mi][ni][0] * inv0, o[mi][ni][1] * inv0);
            *reinterpret_cast<__half2*>(&O[(size_t)(gr + 8) * (NH * DV) + col]) =
                __floats2half2_rn(o[mi][ni][2] * inv1, o[mi][ni][3] * inv1);
        }
    }
}

// ---------------- split-K final add ----------------
__global__ __launch_bounds__(256) void add_kernel(float* __restrict__ out,
                                                  const float* __restrict__ o1) {
    int i = (blockIdx.x * 256 + threadIdx.x) * 4;
    float4 a = *reinterpret_cast<float4*>(out + i);
    float4 b = *reinterpret_cast<const float4*>(o1 + i);
    a.x += b.x; a.y += b.y; a.z += b.z; a.w += b.w;
    *reinterpret_cast<float4*>(out + i) = a;
}

// ---------------- launch ----------------
extern "C" void kernel_launch(void* const* d_in, const int* in_sizes, int n_in,
                              void* d_out, int out_size) {
    const float* hidden   = (const float*)d_in[0];
    const float* cosb     = (const float*)d_in[1];
    const float* sinb     = (const float*)d_in[2];
    const float* wq_a     = (const float*)d_in[3];
    const float* q_a_ln_w = (const float*)d_in[4];
    const float* wq_b     = (const float*)d_in[5];
    const float* wkv_a    = (const float*)d_in[6];
    const float* kv_a_ln  = (const float*)d_in[7];
    const float* wkv_b    = (const float*)d_in[8];
    const float* wo       = (const float*)d_in[9];
    float* out = (float*)d_out;

    float *o1;
    __half *qa0, *qa1, *ckv0, *ckv1;
    __half *hidh, *wqaT, *wkvaT, *wqbT, *wkvbT, *woT, *qan, *ckvn, *Qp, *Kp, *Vt, *attn;
    cudaGetSymbolAddress((void**)&qa0,  g_qa0);
    cudaGetSymbolAddress((void**)&qa1,  g_qa1);
    cudaGetSymbolAddress((void**)&ckv0, g_ckv0);
    cudaGetSymbolAddress((void**)&ckv1, g_ckv1);
    cudaGetSymbolAddress((void**)&o1,   g_o1);
    cudaGetSymbolAddress((void**)&hidh, g_hidh);
    cudaGetSymbolAddress((void**)&wqaT, g_wqaT);
    cudaGetSymbolAddress((void**)&wkvaT,g_wkvaT);
    cudaGetSymbolAddress((void**)&wqbT, g_wqbT);
    cudaGetSymbolAddress((void**)&wkvbT,g_wkvbT);
    cudaGetSymbolAddress((void**)&woT,  g_woT);
    cudaGetSymbolAddress((void**)&qan,  g_qan);
    cudaGetSymbolAddress((void**)&ckvn, g_ckvn);
    cudaGetSymbolAddress((void**)&Qp,   g_Q);
    cudaGetSymbolAddress((void**)&Kp,   g_K);
    cudaGetSymbolAddress((void**)&Vt,   g_Vt);
    cudaGetSymbolAddress((void**)&attn, g_attn);

    cudaFuncSetAttribute(hgemm_plain, cudaFuncAttributeMaxDynamicSharedMemorySize,
                         HG_SMEM_BYTES);
    cudaFuncSetAttribute(hgemm_fused, cudaFuncAttributeMaxDynamicSharedMemorySize,
                         HG_SMEM_BYTES);
    cudaFuncSetAttribute(flash6, cudaFuncAttributeMaxDynamicSharedMemorySize,
                         FLASH6_SMEM_BYTES);

    dim3 blk(256);
    const int KH = HID / 2;   // 1280

    // 1) convert
    {
        CV6 cp;
        const float* srcs[6] = { wq_a, wkv_a, wq_b, wkv_b, wo, hidden };
        __half* dsts[6] = { wqaT, wkvaT, wqbT, wkvbT, woT, hidh };
        int Ks[6] = { HID, HID, QA_DIM, CKV_DIM, NH*DV, SEQ*HID };
        int Ns[6] = { QA_DIM, KVA_DIM, QB_DIM, KVB_DIM, OUT_DIM, 0 };
        int acc = 0;
        for (int i = 0; i < 6; i++) {
            cp.src[i] = srcs[i]; cp.dst[i] = dsts[i];
            cp.K[i] = Ks[i]; cp.N[i] = Ns[i];
            cp.bstart[i] = acc;
            if (i < 5) {
                cp.trans[i] = 1;
                cp.nbx[i] = (Ns[i] + 63) / 64;
                acc += (Ks[i] / 64) * cp.nbx[i];
            } else {
                cp.trans[i] = 0;
                cp.nbx[i] = 1;
                acc += Ks[i] / 4096;
            }
        }
        cp.bstart[6] = acc;
        convtrans<<<acc, blk>>>(cp);
    }

    // 2) merged split-K down-projections (half out)
    {
        GP4 p;
        p.nprob = 4;
        p.cosp = cosb; p.sinp = sinb; p.Qp = Qp; p.Kp = Kp; p.Vtp = Vt;
        p.A[0] = hidh;      p.B[0] = wqaT;       p.C[0] = (float*)qa0;
        p.N[0] = QA_DIM;  p.K[0] = KH; p.lda[0] = HID; p.ldb[0] = HID;
        p.nbx[0] = QA_DIM / 128; p.mode[0] = 1;
        p.A[1] = hidh + KH; p.B[1] = wqaT + KH;  p.C[1] = (float*)qa1;
        p.N[1] = QA_DIM;  p.K[1] = KH; p.lda[1] = HID; p.ldb[1] = HID;
        p.nbx[1] = QA_DIM / 128; p.mode[1] = 1;
        p.A[2] = hidh;      p.B[2] = wkvaT;      p.C[2] = (float*)ckv0;
        p.N[2] = KVA_DIM; p.K[2] = KH; p.lda[2] = HID; p.ldb[2] = HID;
        p.nbx[2] = (KVA_DIM + 127) / 128; p.mode[2] = 1;
        p.A[3] = hidh + KH; p.B[3] = wkvaT + KH; p.C[3] = (float*)ckv1;
        p.N[3] = KVA_DIM; p.K[3] = KH; p.lda[3] = HID; p.ldb[3] = HID;
        p.nbx[3] = (KVA_DIM + 127) / 128; p.mode[3] = 1;
        int nb0 = p.nbx[0] * (SEQ / 128);
        int nb2 = p.nbx[2] * (SEQ / 128);
        p.bstart[0] = 0; p.bstart[1] = nb0;
        p.bstart[2] = 2 * nb0; p.bstart[3] = 2 * nb0 + nb2;
        hgemm_plain<<<2 * nb0 + 2 * nb2, blk, HG_SMEM_BYTES>>>(p);
    }
    // 3) fused norms + rope (+ K rope broadcast)
    norm_rope<<<SEQ, 256>>>(qa0, qa1, q_a_ln_w, ckv0, ckv1, kv_a_ln,
                            cosb, sinb, qan, ckvn, Kp);
    // 4) merged up-projections, FUSED epilogues (Q rope / K / Vt)
    {
        GP4 p;
        p.nprob = 2;
        p.cosp = cosb; p.sinp = sinb; p.Qp = Qp; p.Kp = Kp; p.Vtp = Vt;
        p.A[0] = qan;  p.B[0] = wqbT;  p.C[0] = nullptr;
        p.N[0] = QB_DIM;  p.K[0] = QA_DIM; p.lda[0] = QA_DIM; p.ldb[0] = QA_DIM;
        p.nbx[0] = QB_DIM / 128; p.mode[0] = 2;
        p.A[1] = ckvn; p.B[1] = wkvbT; p.C[1] = nullptr;
        p.N[1] = KVB_DIM; p.K[1] = CKV_DIM; p.lda[1] = CKV_DIM; p.ldb[1] = CKV_DIM;
        p.nbx[1] = KVB_DIM / 128; p.mode[1] = 3;
        p.A[2] = p.A[0]; p.B[2] = p.B[0]; p.C[2] = p.C[0];
        p.N[2] = p.N[0]; p.K[2] = p.K[0]; p.lda[2] = p.lda[0]; p.ldb[2] = p.ldb[0];
        p.nbx[2] = 1; p.mode[2] = 2;
        p.A[3] = p.A[0]; p.B[3] = p.B[0]; p.C[3] = p.C[0];
        p.N[3] = p.N[0]; p.K[3] = p.K[0]; p.lda[3] = p.lda[0]; p.ldb[3] = p.ldb[0];
        p.nbx[3] = 1; p.mode[3] = 2;
        int nb0 = p.nbx[0] * (SEQ / 128);
        int nb1 = p.nbx[1] * (SEQ / 128);
        p.bstart[0] = 0; p.bstart[1] = nb0;
        p.bstart[2] = nb0 + nb1; p.bstart[3] = nb0 + nb1;
        hgemm_fused<<<nb0 + nb1, blk, HG_SMEM_BYTES>>>(p);
    }
    // 5) flash attention
    flash6<<<dim3(SEQ / 256, NH), blk, FLASH6_SMEM_BYTES>>>(Qp, Kp, Vt, attn);
    // 6) attn @ wo, split-K x2 (fp32 out)
    {
        const int KW = (NH * DV) / 2;   // 1280
        GP4 p;
        p.nprob = 2;
        p.cosp = cosb; p.sinp = sinb; p.Qp = Qp; p.Kp = Kp; p.Vtp = Vt;
        p.A[0] = attn;      p.B[0] = woT;       p.C[0] = out;
        p.N[0] = OUT_DIM; p.K[0] = KW; p.lda[0] = NH * DV; p.ldb[0] = NH * DV;
        p.nbx[0] = OUT_DIM / 128; p.mode[0] = 0;
        p.A[1] = attn + KW; p.B[1] = woT + KW;  p.C[1] = o1;
        p.N[1] = OUT_DIM; p.K[1] = KW; p.lda[1] = NH * DV; p.ldb[1] = NH * DV;
        p.nbx[1] = OUT_DIM / 128; p.mode[1] = 0;
        p.A[2] = p.A[0]; p.B[2] = p.B[0]; p.C[2] = p.C[0];
        p.N[2] = p.N[0]; p.K[2] = p.K[0]; p.lda[2] = p.lda[0]; p.ldb[2] = p.ldb[0];
        p.nbx[2] = 1; p.mode[2] = 0;
        p.A[3] = p.A[0]; p.B[3] = p.B[0]; p.C[3] = p.C[0];
        p.N[3] = p.N[0]; p.K[3] = p.K[0]; p.lda[3] = p.lda[0]; p.ldb[3] = p.ldb[0];
        p.nbx[3] = 1; p.mode[3] = 0;
        int nb = p.nbx[0] * (SEQ / 128);
        p.bstart[0] = 0; p.bstart[1] = nb;
        p.bstart[2] = 2 * nb; p.bstart[3] = 2 * nb;
        hgemm_plain<<<2 * nb, blk, HG_SMEM_BYTES>>>(p);
    }
    // 7) out += o1
    add_kernel<<<(SEQ * OUT_DIM) / (256 * 4), blk>>>(out, o1);
}

// round 17
// speedup vs baseline: 1.1294x; 1.0993x over previous
#include <cuda_runtime.h>
#include <cuda_fp16.h>
#include <math.h>
#include <stdint.h>

// ---------------- problem constants ----------------
#define SEQ 2048
#define HID 2560
#define NH 40
#define DQK 96
#define DV 64
#define RD 32
#define QA_DIM 768
#define KVA_DIM 288
#define CKV_DIM 256
#define QB_DIM (NH*DQK)         // 3840
#define KVB_DIM (NH*(64+DV))    // 5120
#define OUT_DIM 2560
#define EPSV 1e-6f
#define QSCALE_L2E 0.14724602233502312f   // 96^-0.5 * log2(e)

// ---------------- scratch ----------------
__device__ __half g_qa0 [SEQ*QA_DIM];
__device__ __half g_qa1 [SEQ*QA_DIM];
__device__ __half g_ckv0[SEQ*KVA_DIM];
__device__ __half g_ckv1[SEQ*KVA_DIM];
__device__ __half g_hidh[SEQ*HID];
__device__ __half g_wqaT[QA_DIM*HID];
__device__ __half g_wkvaT[KVA_DIM*HID];
__device__ __half g_wqbT[QB_DIM*QA_DIM];
__device__ __half g_wkvbT[KVB_DIM*CKV_DIM];
__device__ __half g_woT [OUT_DIM*(NH*DV)];
__device__ __half g_qan [SEQ*QA_DIM];
__device__ __half g_ckvn[SEQ*CKV_DIM];
__device__ __half g_Q   [NH*SEQ*DQK];
__device__ __half g_K   [NH*SEQ*DQK];
__device__ __half g_Vt  [NH*DV*SEQ];
__device__ __half g_attn[SEQ*NH*DV];

// ---------------- helpers ----------------
__device__ __forceinline__ float ex2f(float x) {
    float r;
    asm("ex2.approx.ftz.f32 %0, %1;" : "=f"(r) : "f"(x));
    return r;
}
__device__ __forceinline__ void cp16(uint32_t dst, const void* src, bool pred) {
    int sz = pred ? 16 : 0;
    asm volatile("cp.async.cg.shared.global [%0], [%1], 16, %2;\n"
                 :: "r"(dst), "l"(src), "r"(sz));
}
__device__ __forceinline__ void cp_commit() {
    asm volatile("cp.async.commit_group;\n");
}
template <int N>
__device__ __forceinline__ void cp_wait() {
    asm volatile("cp.async.wait_group %0;\n" :: "n"(N));
}

#define MMA_F16(c, a, b) \
    asm volatile("mma.sync.aligned.m16n8k16.row.col.f32.f16.f16.f32 " \
                 "{%0,%1,%2,%3},{%4,%5,%6,%7},{%8,%9},{%0,%1,%2,%3};" \
                 : "+f"(c[0]), "+f"(c[1]), "+f"(c[2]), "+f"(c[3]) \
                 : "r"(a[0]), "r"(a[1]), "r"(a[2]), "r"(a[3]), \
                   "r"(b[0]), "r"(b[1]))

#define LDSM4(r, addr) \
    asm volatile("ldmatrix.sync.aligned.m8n8.x4.shared.b16 {%0,%1,%2,%3}, [%4];" \
                 : "=r"((r)[0]), "=r"((r)[1]), "=r"((r)[2]), "=r"((r)[3]) \
                 : "r"(addr))

__device__ __forceinline__ uint32_t packh2(float a, float b) {
    __half2 h = __floats2half2_rn(a, b);
    return *reinterpret_cast<uint32_t*>(&h);
}

// ================= convert / transpose pass =================
struct CV6 {
    const float* src[6];
    __half* dst[6];
    int K[6], N[6];
    int nbx[6];
    int bstart[7];
    int trans[6];
};
__global__ __launch_bounds__(256) void convtrans(CV6 p) {
    __shared__ __half sm[64 * 72];
    int bid = blockIdx.x;
    int pi = 0;
#pragma unroll
    for (int i = 1; i < 6; i++) if (bid >= p.bstart[i]) pi = i;
    int l = bid - p.bstart[pi];
    int tid = threadIdx.x;
    if (p.trans[pi]) {
        int K = p.K[pi], N = p.N[pi];
        int k0 = (l / p.nbx[pi]) * 64;
        int n0 = (l % p.nbx[pi]) * 64;
        const float* src = p.src[pi];
#pragma unroll
        for (int i = 0; i < 4; i++) {
            int idx = tid + i * 256;
            int r = idx >> 4, c4 = idx & 15;
            int n = n0 + c4 * 4;
            if (n < N) {
                float4 v = *reinterpret_cast<const float4*>(
                    &src[(size_t)(k0 + r) * N + n]);
                sm[(c4 * 4 + 0) * 72 + r] = __float2half_rn(v.x);
                sm[(c4 * 4 + 1) * 72 + r] = __float2half_rn(v.y);
                sm[(c4 * 4 + 2) * 72 + r] = __float2half_rn(v.z);
                sm[(c4 * 4 + 3) * 72 + r] = __float2half_rn(v.w);
            }
        }
        __syncthreads();
        __half* dst = p.dst[pi];
#pragma unroll
        for (int i = 0; i < 2; i++) {
            int idx = tid + i * 256;
            int rr = idx >> 3, cc = idx & 7;
            if (n0 + rr < N) {
                uint4 v = *reinterpret_cast<const uint4*>(&sm[rr * 72 + cc * 8]);
                *reinterpret_cast<uint4*>(
                    &dst[(size_t)(n0 + rr) * K + k0 + cc * 8]) = v;
            }
        }
    } else {
        const float* src = p.src[pi];
        __half* dst = p.dst[pi];
        int base = l * 4096;
#pragma unroll
        for (int i = 0; i < 4; i++) {
            int e = base + (tid + i * 256) * 4;
            float4 v = *reinterpret_cast<const float4*>(&src[e]);
            __half2 h0 = __floats2half2_rn(v.x, v.y);
            __half2 h1 = __floats2half2_rn(v.z, v.w);
            *reinterpret_cast<__half2*>(&dst[e]) = h0;
            *reinterpret_cast<__half2*>(&dst[e + 2]) = h1;
        }
    }
}

// ======= shared GEMM config (128x128x64, 3-stage, ldmatrix) ===========
#define HSTR 72
#define HBUF (128*HSTR)
#define HG_SMEM_BYTES (3*2*HBUF*2)      // 110592

struct GP4 {
    const __half* A[4];
    const __half* B[4];   // BT [N][K]
    float*        C[4];
    int N[4], K[4], lda[4], ldb[4], nbx[4], bstart[4];
    int mode[4];          // 0=fp32 out, 1=half out, 4=fp32 atomicAdd; fused: 2=Q, 3=KV
    int nprob;
    const float* cosp;
    const float* sinp;
    __half* Qp;
    __half* Kp;
    __half* Vtp;
};

template <typename EPI>
__device__ __forceinline__ void hgemm_body(const GP4& p, EPI epi) {
    extern __shared__ __half hsm[];
    uint32_t sm_u = (uint32_t)__cvta_generic_to_shared(hsm);

    int bid = blockIdx.x;
    int pi = 0;
#pragma unroll
    for (int i = 1; i < 4; i++)
        if (i < p.nprob && bid >= p.bstart[i]) pi = i;
    const __half* A = p.A[pi];
    const __half* B = p.B[pi];
    int N = p.N[pi], K = p.K[pi], lda = p.lda[pi], ldb = p.ldb[pi];
    int l = bid - p.bstart[pi];
    int row0 = (l / p.nbx[pi]) * 128;
    int col0 = (l % p.nbx[pi]) * 128;

    int tid = threadIdx.x;
    int warp = tid >> 5, lane = tid & 31;
    int wrow = (warp >> 2) * 64;
    int wcol = (warp & 3) * 32;
    int arow = lane & 15;
    int acol = (lane >> 4) * 8;
    int brow = ((lane >> 4) & 1) * 8 + (lane & 7);
    int bcol = ((lane >> 3) & 1) * 8;

    float c[4][4][4];
#pragma unroll
    for (int mi = 0; mi < 4; mi++)
#pragma unroll
        for (int ni = 0; ni < 4; ni++)
#pragma unroll
            for (int r = 0; r < 4; r++) c[mi][ni][r] = 0.f;

    int kt_total = K / 64;

    auto load_tile = [&](int kt, int stg) {
        int k0 = kt * 64;
        uint32_t aD = sm_u + (uint32_t)(stg * 2 * HBUF * 2);
        uint32_t bD = aD + (uint32_t)(HBUF * 2);
#pragma unroll
        for (int i = 0; i < 4; i++) {
            int idx = tid + i * 256;
            int r = idx >> 3, cc = (idx & 7) * 8;
            cp16(aD + (uint32_t)((r * HSTR + cc) * 2),
                 A + (size_t)(row0 + r) * lda + k0 + cc, true);
        }
#pragma unroll
        for (int i = 0; i < 4; i++) {
            int idx = tid + i * 256;
            int r = idx >> 3, cc = (idx & 7) * 8;
            bool pr = (col0 + r) < N;
            const __half* src = pr ? (B + (size_t)(col0 + r) * ldb + k0 + cc) : B;
            cp16(bD + (uint32_t)((r * HSTR + cc) * 2), src, pr);
        }
    };

    load_tile(0, 0); cp_commit();
    load_tile(1, 1); cp_commit();

    int s_cur = 0, s_next = 2;
    for (int kt = 0; kt < kt_total; kt++) {
        cp_wait<1>();
        __syncthreads();
        if (kt + 2 < kt_total) load_tile(kt + 2, s_next);
        cp_commit();

        uint32_t aBase = sm_u + (uint32_t)(s_cur * 2 * HBUF * 2);
        uint32_t bBase = aBase + (uint32_t)(HBUF * 2);
#pragma unroll
        for (int k0 = 0; k0 < 64; k0 += 16) {
            uint32_t a[4][4], bb[2][4];
#pragma unroll
            for (int mi = 0; mi < 4; mi++)
                LDSM4(a[mi], aBase + (uint32_t)(((wrow + mi * 16 + arow) * HSTR
                                                 + k0 + acol) * 2));
#pragma unroll
            for (int nip = 0; nip < 2; nip++)
                LDSM4(bb[nip], bBase + (uint32_t)(((wcol + nip * 16 + brow) * HSTR
                                                   + k0 + bcol) * 2));
#pragma unroll
            for (int mi = 0; mi < 4; mi++)
#pragma unroll
                for (int ni = 0; ni < 4; ni++)
                    MMA_F16(c[mi][ni], a[mi], (&bb[ni >> 1][2 * (ni & 1)]));
        }
        s_cur = (s_cur == 2) ? 0 : s_cur + 1;
        s_next = (s_next == 2) ? 0 : s_next + 1;
    }
    epi(pi, row0, col0, N, c);
}

// ---- plain GEMM (fp32 / half / fp32-atomic epilogue) ----
__global__ __launch_bounds__(256, 2) void hgemm_plain(GP4 p) {
    int tid = threadIdx.x;
    int warp = tid >> 5, lane = tid & 31;
    int g = lane >> 2, t = lane & 3;
    int wrow = (warp >> 2) * 64;
    int wcol = (warp & 3) * 32;
    hgemm_body(p, [&](int pi, int row0, int col0, int N, float c[4][4][4]) {
        int mode = p.mode[pi];
        if (mode == 1) {
            __half* Ch = reinterpret_cast<__half*>(p.C[pi]);
#pragma unroll
            for (int mi = 0; mi < 4; mi++) {
#pragma unroll
                for (int ni = 0; ni < 4; ni++) {
                    int row = row0 + wrow + mi * 16 + g;
                    int col = col0 + wcol + ni * 8 + 2 * t;
                    if (col < N) {
                        *reinterpret_cast<__half2*>(&Ch[(size_t)row * N + col]) =
                            __floats2half2_rn(c[mi][ni][0], c[mi][ni][1]);
                        *reinterpret_cast<__half2*>(&Ch[(size_t)(row + 8) * N + col]) =
                            __floats2half2_rn(c[mi][ni][2], c[mi][ni][3]);
                    }
                }
            }
        } else if (mode == 4) {
            float* C = p.C[pi];
#pragma unroll
            for (int mi = 0; mi < 4; mi++) {
#pragma unroll
                for (int ni = 0; ni < 4; ni++) {
                    int row = row0 + wrow + mi * 16 + g;
                    int col = col0 + wcol + ni * 8 + 2 * t;
                    if (col < N) {
                        atomicAdd(&C[(size_t)row * N + col],       c[mi][ni][0]);
                        atomicAdd(&C[(size_t)row * N + col + 1],   c[mi][ni][1]);
                        atomicAdd(&C[(size_t)(row + 8) * N + col], c[mi][ni][2]);
                        atomicAdd(&C[(size_t)(row + 8) * N + col + 1], c[mi][ni][3]);
                    }
                }
            }
        } else {
            float* C = p.C[pi];
#pragma unroll
            for (int mi = 0; mi < 4; mi++) {
#pragma unroll
                for (int ni = 0; ni < 4; ni++) {
                    int row = row0 + wrow + mi * 16 + g;
                    int col = col0 + wcol + ni * 8 + 2 * t;
                    if (col < N) {
                        float2 v0 = make_float2(c[mi][ni][0], c[mi][ni][1]);
                        float2 v1 = make_float2(c[mi][ni][2], c[mi][ni][3]);
                        *reinterpret_cast<float2*>(&C[(size_t)row * N + col]) = v0;
                        *reinterpret_cast<float2*>(&C[(size_t)(row + 8) * N + col]) = v1;
                    }
                }
            }
        }
    });
}

// ---- fused GEMM (Q-rope / K+Vt epilogues) ----
__global__ __launch_bounds__(256, 2) void hgemm_fused(GP4 p) {
    extern __shared__ __half hsm[];
    int tid = threadIdx.x;
    int warp = tid >> 5, lane = tid & 31;
    int g = lane >> 2, t = lane & 3;
    int wrow = (warp >> 2) * 64;
    int wcol = (warp & 3) * 32;
    hgemm_body(p, [&](int pi, int row0, int col0, int N, float c[4][4][4]) {
        int mode = p.mode[pi];
        if (mode == 2) {
            int cb = col0 + wcol;
            int h = cb / 96;
            int rem = cb % 96;
            bool ropeBlk = (rem == 64);
            __half* Qg = p.Qp;
#pragma unroll
            for (int mi = 0; mi < 4; mi++) {
#pragma unroll
                for (int rr = 0; rr < 2; rr++) {
                    int srow = row0 + wrow + mi * 16 + g + 8 * rr;
                    const float* cosr = p.cosp + (size_t)srow * RD;
                    const float* sinr = p.sinp + (size_t)srow * RD;
#pragma unroll
                    for (int ni = 0; ni < 4; ni++) {
                        int dd = ni * 8 + 2 * t;
                        float v0 = c[mi][ni][2 * rr];
                        float v1 = c[mi][ni][2 * rr + 1];
                        if (ropeBlk) {
                            float cs0 = cosr[dd], sn0 = sinr[dd];
                            float cs1 = cosr[dd + 1], sn1 = sinr[dd + 1];
                            float r0, r1;
                            if (ni < 2) {
                                r0 = -c[mi][ni + 2][2 * rr];
                                r1 = -c[mi][ni + 2][2 * rr + 1];
                            } else {
                                r0 = c[mi][ni - 2][2 * rr];
                                r1 = c[mi][ni - 2][2 * rr + 1];
                            }
                            v0 = v0 * cs0 + r0 * sn0;
                            v1 = v1 * cs1 + r1 * sn1;
                        }
                        *reinterpret_cast<__half2*>(
                            &Qg[((size_t)h * SEQ + srow) * DQK + rem + dd]) =
                            __floats2half2_rn(v0 * QSCALE_L2E, v1 * QSCALE_L2E);
                    }
                }
            }
        } else {
            int h = col0 / 128;
            __half* Kg = p.Kp;
            if (wcol < 64) {
#pragma unroll
                for (int mi = 0; mi < 4; mi++) {
#pragma unroll
                    for (int ni = 0; ni < 4; ni++) {
                        int d = wcol + ni * 8 + 2 * t;
                        int row = row0 + wrow + mi * 16 + g;
                        *reinterpret_cast<__half2*>(
                            &Kg[((size_t)h * SEQ + row) * DQK + d]) =
                            __floats2half2_rn(c[mi][ni][0], c[mi][ni][1]);
                        *reinterpret_cast<__half2*>(
                            &Kg[((size_t)h * SEQ + row + 8) * DQK + d]) =
                            __floats2half2_rn(c[mi][ni][2], c[mi][ni][3]);
                    }
                }
            }
            __syncthreads();
            if (wcol >= 64) {
#pragma unroll
                for (int mi = 0; mi < 4; mi++) {
#pragma unroll
                    for (int ni = 0; ni < 4; ni++) {
                        int d = wcol - 64 + ni * 8 + 2 * t;
                        int sl = wrow + mi * 16 + g;
                        hsm[d * 136 + sl] = __float2half_rn(c[mi][ni][0]);
                        hsm[(d + 1) * 136 + sl] = __float2half_rn(c[mi][ni][1]);
                        hsm[d * 136 + sl + 8] = __float2half_rn(c[mi][ni][2]);
                        hsm[(d + 1) * 136 + sl + 8] = __float2half_rn(c[mi][ni][3]);
                    }
                }
            }
            __syncthreads();
            __half* Vtg = p.Vtp;
            for (int i = tid; i < 64 * 16; i += 256) {
                int d = i >> 4, sc8 = (i & 15) * 8;
                uint4 v = *reinterpret_cast<const uint4*>(&hsm[d * 136 + sc8]);
                *reinterpret_cast<uint4*>(
                    &Vtg[((size_t)(h * 64 + d)) * SEQ + row0 + sc8]) = v;
            }
        }
    });
}

// ---------------- fused norms + rope + K-rope broadcast ----------------
__global__ __launch_bounds__(256) void norm_rope(
    const __half* __restrict__ qa0, const __half* __restrict__ qa1,
    const float* __restrict__ qw,
    const __half* __restrict__ ckv0, const __half* __restrict__ ckv1,
    const float* __restrict__ kvw,
    const float* __restrict__ cosb, const float* __restrict__ sinb,
    __half* __restrict__ qan, __half* __restrict__ ckvn,
    __half* __restrict__ Kp) {
    int s = blockIdx.x;
    int tid = threadIdx.x;
    int lane = tid & 31, wid = tid >> 5;
    __shared__ float warp_s[8];
    __shared__ float snorm;
    __shared__ float kp[RD];

    float v[3];
    float ss = 0.f;
#pragma unroll
    for (int i = 0; i < 3; i++) {
        int c = tid + i * 256;
        v[i] = __half2float(qa0[(size_t)s * QA_DIM + c])
             + __half2float(qa1[(size_t)s * QA_DIM + c]);
        ss += v[i] * v[i];
    }
    for (int off = 16; off > 0; off >>= 1) ss += __shfl_down_sync(0xffffffffu, ss, off);
    if (lane == 0) warp_s[wid] = ss;
    __syncthreads();
    if (tid == 0) {
        float tt = 0.f;
#pragma unroll
        for (int i = 0; i < 8; i++) tt += warp_s[i];
        snorm = rsqrtf(tt / (float)QA_DIM + EPSV);
    }
    __syncthreads();
    float rr = snorm;
#pragma unroll
    for (int i = 0; i < 3; i++) {
        int c = tid + i * 256;
        qan[(size_t)s * QA_DIM + c] = __float2half_rn(v[i] * rr * qw[c]);
    }
    __syncthreads();

    float w = __half2float(ckv0[(size_t)s * KVA_DIM + tid])
            + __half2float(ckv1[(size_t)s * KVA_DIM + tid]);
    float ss2 = w * w;
    for (int off = 16; off > 0; off >>= 1) ss2 += __shfl_down_sync(0xffffffffu, ss2, off);
    if (lane == 0) warp_s[wid] = ss2;
    __syncthreads();
    if (tid == 0) {
        float tt = 0.f;
#pragma unroll
        for (int i = 0; i < 8; i++) tt += warp_s[i];
        snorm = rsqrtf(tt / (float)CKV_DIM + EPSV);
    }
    if (tid < RD) {
        size_t base = (size_t)s * KVA_DIM + CKV_DIM;
        float x = __half2float(ckv0[base + tid]) + __half2float(ckv1[base + tid]);
        int pp = (tid < 16) ? tid + 16 : tid - 16;
        float xr = __half2float(ckv0[base + pp]) + __half2float(ckv1[base + pp]);
        float rot = (tid < 16) ? -xr : xr;
        kp[tid] = x * cosb[(size_t)s * RD + tid]
                + rot * sinb[(size_t)s * RD + tid];
    }
    __syncthreads();
    ckvn[(size_t)s * CKV_DIM + tid] = __float2half_rn(w * snorm * kvw[tid]);
    for (int i = tid; i < NH * RD; i += 256) {
        int h = i >> 5, d = i & 31;
        Kp[((size_t)h * SEQ + s) * DQK + 64 + d] = __float2half_rn(kp[d]);
    }
}

// ===== FP16 flash attention: 256x64, 3-stage, Q frags hoisted, P in regs ====
// 1D grid: all longest q-tiles first (bid/NH gives descending qt).
#define FQS 104
#define FPS_V 72
#define FQS_H (256*FQS)
#define FKS_H (64*FQS)
#define FVS_H (64*FPS_V)
#define FLASH6_SMEM_BYTES ((FQS_H + 3*FKS_H + 3*FVS_H) * 2)   // 120832

__device__ __forceinline__ void flash_loadKV(const __half* __restrict__ Kh,
                                             const __half* __restrict__ Vth,
                                             int k0g, uint32_t ks_u, uint32_t vs_u,
                                             int tid) {
#pragma unroll
    for (int i = 0; i < 3; i++) {
        int idx = tid + i * 256;
        int r = idx / 12, cc = (idx % 12) * 8;
        cp16(ks_u + (uint32_t)((r * FQS + cc) * 2),
             Kh + (size_t)(k0g + r) * DQK + cc, true);
    }
#pragma unroll
    for (int i = 0; i < 2; i++) {
        int idx = tid + i * 256;
        int r = idx >> 3, cc = (idx & 7) * 8;
        cp16(vs_u + (uint32_t)((r * FPS_V + cc) * 2),
             Vth + (size_t)r * SEQ + k0g + cc, true);
    }
}

__global__ __launch_bounds__(256, 1) void flash6(const __half* __restrict__ Q,
                                                 const __half* __restrict__ K,
                                                 const __half* __restrict__ Vt,
                                                 __half* __restrict__ O) {
    extern __shared__ __half smh[];
    __half* Qs = smh;
    __half* Ks = Qs + FQS_H;
    __half* Vs = Ks + 3 * FKS_H;
    uint32_t ks_u = (uint32_t)__cvta_generic_to_shared(Ks);
    uint32_t vs_u = (uint32_t)__cvta_generic_to_shared(Vs);
    uint32_t qs_u = (uint32_t)__cvta_generic_to_shared(Qs);

    // 1D sorted grid: blocks 0..NH-1 get qt = NQT-1 (longest), etc.
    int bid = blockIdx.x;
    const int NQT = SEQ / 256;
    int qt = (NQT - 1) - bid / NH;
    int h = bid % NH;
    int q0 = qt * 256;
    int tid = threadIdx.x, warp = tid >> 5, lane = tid & 31;
    int g = lane >> 2, t = lane & 3;
    int wrb = warp * 32;
    int wr = wrb + g;
    int arow = lane & 15;
    int acol = (lane >> 4) * 8;
    int brow = ((lane >> 4) & 1) * 8 + (lane & 7);
    int bcol = ((lane >> 3) & 1) * 8;
    const __half* Qh = Q + (size_t)h * SEQ * DQK;
    const __half* Kh = K + (size_t)h * SEQ * DQK;
    const __half* Vth = Vt + (size_t)h * DV * SEQ;

#pragma unroll
    for (int i = 0; i < 12; i++) {
        int idx = tid + i * 256;
        int r = idx / 12, cc = (idx % 12) * 8;
        cp16(qs_u + (uint32_t)((r * FQS + cc) * 2),
             Qh + (size_t)(q0 + r) * DQK + cc, true);
    }

    float m0[2], m1[2], l0[2], l1[2];
#pragma unroll
    for (int mi = 0; mi < 2; mi++) {
        m0[mi] = -1e30f; m1[mi] = -1e30f; l0[mi] = 0.f; l1[mi] = 0.f;
    }
    float o[2][8][4];
#pragma unroll
    for (int mi = 0; mi < 2; mi++)
#pragma unroll
        for (int ni = 0; ni < 8; ni++)
#pragma unroll
            for (int r = 0; r < 4; r++) o[mi][ni][r] = 0.f;

    uint32_t qa[2][6][4];

    int nkt = 4 * qt + 4;
    flash_loadKV(Kh, Vth, 0, ks_u, vs_u, tid);
    cp_commit();
    if (1 < nkt) flash_loadKV(Kh, Vth, 64, ks_u + (uint32_t)(FKS_H * 2),
                              vs_u + (uint32_t)(FVS_H * 2), tid);
    cp_commit();

    int s_cur = 0, s_next = 2;
    for (int kt = 0; kt < nkt; kt++) {
        cp_wait<1>();
        __syncthreads();
        if (kt == 0) {
#pragma unroll
            for (int mi = 0; mi < 2; mi++)
#pragma unroll
                for (int ks = 0; ks < 6; ks++)
                    LDSM4(qa[mi][ks],
                          qs_u + (uint32_t)(((wrb + mi * 16 + arow) * FQS
                                             + ks * 16 + acol) * 2));
        }
        if (kt + 2 < nkt)
            flash_loadKV(Kh, Vth, (kt + 2) * 64,
                         ks_u + (uint32_t)(s_next * FKS_H * 2),
                         vs_u + (uint32_t)(s_next * FVS_H * 2), tid);
        cp_commit();

        uint32_t kBase = ks_u + (uint32_t)(s_cur * FKS_H * 2);
        uint32_t vBase = vs_u + (uint32_t)(s_cur * FVS_H * 2);

        float s[2][8][4];
#pragma unroll
        for (int mi = 0; mi < 2; mi++)
#pragma unroll
            for (int ni = 0; ni < 8; ni++)
#pragma unroll
                for (int r = 0; r < 4; r++) s[mi][ni][r] = 0.f;

#pragma unroll
        for (int ks = 0; ks < 6; ks++) {
            uint32_t kb[4][4];
#pragma unroll
            for (int nip = 0; nip < 4; nip++)
                LDSM4(kb[nip], kBase + (uint32_t)(((nip * 16 + brow) * FQS
                                                   + ks * 16 + bcol) * 2));
#pragma unroll
            for (int ni = 0; ni < 8; ni++) {
                MMA_F16(s[0][ni], qa[0][ks], (&kb[ni >> 1][2 * (ni & 1)]));
                MMA_F16(s[1][ni], qa[1][ks], (&kb[ni >> 1][2 * (ni & 1)]));
            }
        }

        int k0g = kt * 64;
        if (k0g + 63 > q0) {
#pragma unroll
            for (int mi = 0; mi < 2; mi++) {
                int rg = q0 + wr + mi * 16;
#pragma unroll
                for (int ni = 0; ni < 8; ni++) {
                    int col = k0g + ni * 8 + 2 * t;
                    if (col > rg)         s[mi][ni][0] = -1e30f;
                    if (col + 1 > rg)     s[mi][ni][1] = -1e30f;
                    if (col > rg + 8)     s[mi][ni][2] = -1e30f;
                    if (col + 1 > rg + 8) s[mi][ni][3] = -1e30f;
                }
            }
        }

        uint32_t ph[2][4][4];
#pragma unroll
        for (int mi = 0; mi < 2; mi++) {
            float mx0 = -1e30f, mx1 = -1e30f;
#pragma unroll
            for (int ni = 0; ni < 8; ni++) {
                mx0 = fmaxf(mx0, fmaxf(s[mi][ni][0], s[mi][ni][1]));
                mx1 = fmaxf(mx1, fmaxf(s[mi][ni][2], s[mi][ni][3]));
            }
            mx0 = fmaxf(mx0, __shfl_xor_sync(0xffffffffu, mx0, 1));
            mx0 = fmaxf(mx0, __shfl_xor_sync(0xffffffffu, mx0, 2));
            mx1 = fmaxf(mx1, __shfl_xor_sync(0xffffffffu, mx1, 1));
            mx1 = fmaxf(mx1, __shfl_xor_sync(0xffffffffu, mx1, 2));

            float mn0 = fmaxf(m0[mi], mx0), mn1 = fmaxf(m1[mi], mx1);
            float al0 = ex2f(m0[mi] - mn0), al1 = ex2f(m1[mi] - mn1);
            m0[mi] = mn0; m1[mi] = mn1;
            l0[mi] *= al0; l1[mi] *= al1;

            float sum0 = 0.f, sum1 = 0.f;
#pragma unroll
            for (int ni = 0; ni < 8; ni++) {
                float p0 = ex2f(s[mi][ni][0] - mn0);
                float p1 = ex2f(s[mi][ni][1] - mn0);
                float p2 = ex2f(s[mi][ni][2] - mn1);
                float p3 = ex2f(s[mi][ni][3] - mn1);
                sum0 += p0 + p1;
                sum1 += p2 + p3;
                int ks = ni >> 1, half8 = ni & 1;
                ph[mi][ks][2 * half8]     = packh2(p0, p1);
                ph[mi][ks][2 * half8 + 1] = packh2(p2, p3);
                o[mi][ni][0] *= al0; o[mi][ni][1] *= al0;
                o[mi][ni][2] *= al1; o[mi][ni][3] *= al1;
            }
            sum0 += __shfl_xor_sync(0xffffffffu, sum0, 1);
            sum0 += __shfl_xor_sync(0xffffffffu, sum0, 2);
            sum1 += __shfl_xor_sync(0xffffffffu, sum1, 1);
            sum1 += __shfl_xor_sync(0xffffffffu, sum1, 2);
            l0[mi] += sum0; l1[mi] += sum1;
        }

#pragma unroll
        for (int ks = 0; ks < 4; ks++) {
            uint32_t vb[4][4];
#pragma unroll
            for (int nip = 0; nip < 4; nip++)
                LDSM4(vb[nip], vBase + (uint32_t)(((nip * 16 + brow) * FPS_V
                                                   + ks * 16 + bcol) * 2));
#pragma unroll
            for (int ni = 0; ni < 8; ni++) {
                MMA_F16(o[0][ni], ph[0][ks], (&vb[ni >> 1][2 * (ni & 1)]));
                MMA_F16(o[1][ni], ph[1][ks], (&vb[ni >> 1][2 * (ni & 1)]));
            }
        }
        s_cur = (s_cur == 2) ? 0 : s_cur + 1;
        s_next = (s_next == 2) ? 0 : s_next + 1;
    }

#pragma unroll
    for (int mi = 0; mi < 2; mi++) {
        float inv0 = 1.f / l0[mi], inv1 = 1.f / l1[mi];
        int gr = q0 + wr + mi * 16;
#pragma unroll
        for (int ni = 0; ni < 8; ni++) {
            int col = h * DV + ni * 8 + 2 * t;
            *reinterpret_cast<__half2*>(&O[(size_t)gr * (NH * DV) + col]) =
                __floats2half2_rn(o[mi][ni][0] * inv0, o[mi][ni][1] * inv0);
            *reinterpret_cast<__half2*>(&O[(size_t)(gr + 8) * (NH * DV) + col]) =
                __floats2half2_rn(o[mi][ni][2] * inv1, o[mi][ni][3] * inv1);
        }
    }
}

// ---------------- launch ----------------
extern "C" void kernel_launch(void* const* d_in, const int* in_sizes, int n_in,
                              void* d_out, int out_size) {
    const float* hidden   = (const float*)d_in[0];
    const float* cosb     = (const float*)d_in[1];
    const float* sinb     = (const float*)d_in[2];
    const float* wq_a     = (const float*)d_in[3];
    const float* q_a_ln_w = (const float*)d_in[4];
    const float* wq_b     = (const float*)d_in[5];
    const float* wkv_a    = (const float*)d_in[6];
    const float* kv_a_ln  = (const float*)d_in[7];
    const float* wkv_b    = (const float*)d_in[8];
    const float* wo       = (const float*)d_in[9];
    float* out = (float*)d_out;

    __half *qa0, *qa1, *ckv0, *ckv1;
    __half *hidh, *wqaT, *wkvaT, *wqbT, *wkvbT, *woT, *qan, *ckvn, *Qp, *Kp, *Vt, *attn;
    cudaGetSymbolAddress((void**)&qa0,  g_qa0);
    cudaGetSymbolAddress((void**)&qa1,  g_qa1);
    cudaGetSymbolAddress((void**)&ckv0, g_ckv0);
    cudaGetSymbolAddress((void**)&ckv1, g_ckv1);
    cudaGetSymbolAddress((void**)&hidh, g_hidh);
    cudaGetSymbolAddress((void**)&wqaT, g_wqaT);
    cudaGetSymbolAddress((void**)&wkvaT,g_wkvaT);
    cudaGetSymbolAddress((void**)&wqbT, g_wqbT);
    cudaGetSymbolAddress((void**)&wkvbT,g_wkvbT);
    cudaGetSymbolAddress((void**)&woT,  g_woT);
    cudaGetSymbolAddress((void**)&qan,  g_qan);
    cudaGetSymbolAddress((void**)&ckvn, g_ckvn);
    cudaGetSymbolAddress((void**)&Qp,   g_Q);
    cudaGetSymbolAddress((void**)&Kp,   g_K);
    cudaGetSymbolAddress((void**)&Vt,   g_Vt);
    cudaGetSymbolAddress((void**)&attn, g_attn);

    cudaFuncSetAttribute(hgemm_plain, cudaFuncAttributeMaxDynamicSharedMemorySize,
                         HG_SMEM_BYTES);
    cudaFuncSetAttribute(hgemm_fused, cudaFuncAttributeMaxDynamicSharedMemorySize,
                         HG_SMEM_BYTES);
    cudaFuncSetAttribute(flash6, cudaFuncAttributeMaxDynamicSharedMemorySize,
                         FLASH6_SMEM_BYTES);

    dim3 blk(256);
    const int KH = HID / 2;   // 1280

    // 0) zero the output (split-K accumulates via atomics)
    cudaMemsetAsync(out, 0, (size_t)SEQ * OUT_DIM * sizeof(float));

    // 1) convert
    {
        CV6 cp;
        const float* srcs[6] = { wq_a, wkv_a, wq_b, wkv_b, wo, hidden };
        __half* dsts[6] = { wqaT, wkvaT, wqbT, wkvbT, woT, hidh };
        int Ks[6] = { HID, HID, QA_DIM, CKV_DIM, NH*DV, SEQ*HID };
        int Ns[6] = { QA_DIM, KVA_DIM, QB_DIM, KVB_DIM, OUT_DIM, 0 };
        int acc = 0;
        for (int i = 0; i < 6; i++) {
            cp.src[i] = srcs[i]; cp.dst[i] = dsts[i];
            cp.K[i] = Ks[i]; cp.N[i] = Ns[i];
            cp.bstart[i] = acc;
            if (i < 5) {
                cp.trans[i] = 1;
                cp.nbx[i] = (Ns[i] + 63) / 64;
                acc += (Ks[i] / 64) * cp.nbx[i];
            } else {
                cp.trans[i] = 0;
                cp.nbx[i] = 1;
                acc += Ks[i] / 4096;
            }
        }
        cp.bstart[6] = acc;
        convtrans<<<acc, blk>>>(cp);
    }

    // 2) merged split-K down-projections (half out)
    {
        GP4 p;
        p.nprob = 4;
        p.cosp = cosb; p.sinp = sinb; p.Qp = Qp; p.Kp = Kp; p.Vtp = Vt;
        p.A[0] = hidh;      p.B[0] = wqaT;       p.C[0] = (float*)qa0;
        p.N[0] = QA_DIM;  p.K[0] = KH; p.lda[0] = HID; p.ldb[0] = HID;
        p.nbx[0] = QA_DIM / 128; p.mode[0] = 1;
        p.A[1] = hidh + KH; p.B[1] = wqaT + KH;  p.C[1] = (float*)qa1;
        p.N[1] = QA_DIM;  p.K[1] = KH; p.lda[1] = HID; p.ldb[1] = HID;
        p.nbx[1] = QA_DIM / 128; p.mode[1] = 1;
        p.A[2] = hidh;      p.B[2] = wkvaT;      p.C[2] = (float*)ckv0;
        p.N[2] = KVA_DIM; p.K[2] = KH; p.lda[2] = HID; p.ldb[2] = HID;
        p.nbx[2] = (KVA_DIM + 127) / 128; p.mode[2] = 1;
        p.A[3] = hidh + KH; p.B[3] = wkvaT + KH; p.C[3] = (float*)ckv1;
        p.N[3] = KVA_DIM; p.K[3] = KH; p.lda[3] = HID; p.ldb[3] = HID;
        p.nbx[3] = (KVA_DIM + 127) / 128; p.mode[3] = 1;
        int nb0 = p.nbx[0] * (SEQ / 128);
        int nb2 = p.nbx[2] * (SEQ / 128);
        p.bstart[0] = 0; p.bstart[1] = nb0;
        p.bstart[2] = 2 * nb0; p.bstart[3] = 2 * nb0 + nb2;
        hgemm_plain<<<2 * nb0 + 2 * nb2, blk, HG_SMEM_BYTES>>>(p);
    }
    // 3) fused norms + rope (+ K rope broadcast)
    norm_rope<<<SEQ, 256>>>(qa0, qa1, q_a_ln_w, ckv0, ckv1, kv_a_ln,
                            cosb, sinb, qan, ckvn, Kp);
    // 4) merged up-projections, FUSED epilogues (Q rope / K / Vt)
    {
        GP4 p;
        p.nprob = 2;
        p.cosp = cosb; p.sinp = sinb; p.Qp = Qp; p.Kp = Kp; p.Vtp = Vt;
        p.A[0] = qan;  p.B[0] = wqbT;  p.C[0] = nullptr;
        p.N[0] = QB_DIM;  p.K[0] = QA_DIM; p.lda[0] = QA_DIM; p.ldb[0] = QA_DIM;
        p.nbx[0] = QB_DIM / 128; p.mode[0] = 2;
        p.A[1] = ckvn; p.B[1] = wkvbT; p.C[1] = nullptr;
        p.N[1] = KVB_DIM; p.K[1] = CKV_DIM; p.lda[1] = CKV_DIM; p.ldb[1] = CKV_DIM;
        p.nbx[1] = KVB_DIM / 128; p.mode[1] = 3;
        p.A[2] = p.A[0]; p.B[2] = p.B[0]; p.C[2] = p.C[0];
        p.N[2] = p.N[0]; p.K[2] = p.K[0]; p.lda[2] = p.lda[0]; p.ldb[2] = p.ldb[0];
        p.nbx[2] = 1; p.mode[2] = 2;
        p.A[3] = p.A[0]; p.B[3] = p.B[0]; p.C[3] = p.C[0];
        p.N[3] = p.N[0]; p.K[3] = p.K[0]; p.lda[3] = p.lda[0]; p.ldb[3] = p.ldb[0];
        p.nbx[3] = 1; p.mode[3] = 2;
        int nb0 = p.nbx[0] * (SEQ / 128);
        int nb1 = p.nbx[1] * (SEQ / 128);
        p.bstart[0] = 0; p.bstart[1] = nb0;
        p.bstart[2] = nb0 + nb1; p.bstart[3] = nb0 + nb1;
        hgemm_fused<<<nb0 + nb1, blk, HG_SMEM_BYTES>>>(p);
    }
    // 5) flash attention (1D sorted grid: longest q-tiles first)
    flash6<<<(SEQ / 256) * NH, blk, FLASH6_SMEM_BYTES>>>(Qp, Kp, Vt, attn);
    // 6) attn @ wo, split-K x2 accumulating into zeroed out via atomics
    {
        const int KW = (NH * DV) / 2;   // 1280
        GP4 p;
        p.nprob = 2;
        p.cosp = cosb; p.sinp = sinb; p.Qp = Qp; p.Kp = Kp; p.Vtp = Vt;
        p.A[0] = attn;      p.B[0] = woT;       p.C[0] = out;
        p.N[0] = OUT_DIM; p.K[0] = KW; p.lda[0] = NH * DV; p.ldb[0] = NH * DV;
        p.nbx[0] = OUT_DIM / 128; p.mode[0] = 4;
        p.A[1] = attn + KW; p.B[1] = woT + KW;  p.C[1] = out;
        p.N[1] = OUT_DIM; p.K[1] = KW; p.lda[1] = NH * DV; p.ldb[1] = NH * DV;
        p.nbx[1] = OUT_DIM / 128; p.mode[1] = 4;
        p.A[2] = p.A[0]; p.B[2] = p.B[0]; p.C[2] = p.C[0];
        p.N[2] = p.N[0]; p.K[2] = p.K[0]; p.lda[2] = p.lda[0]; p.ldb[2] = p.ldb[0];
        p.nbx[2] = 1; p.mode[2] = 4;
        p.A[3] = p.A[0]; p.B[3] = p.B[0]; p.C[3] = p.C[0];
        p.N[3] = p.N[0]; p.K[3] = p.K[0]; p.lda[3] = p.lda[0]; p.ldb[3] = p.ldb[0];
        p.nbx[3] = 1; p.mode[3] = 4;
        int nb = p.nbx[0] * (SEQ / 128);
        p.bstart[0] = 0; p.bstart[1] = nb;
        p.bstart[2] = 2 * nb; p.bstart[3] = 2 * nb;
        hgemm_plain<<<2 * nb, blk, HG_SMEM_BYTES>>>(p);
    }
}